// round 1
// baseline (speedup 1.0000x reference)
#include <cuda_runtime.h>
#include <math.h>

// Problem constants
#define BATCH   4
#define SEQ     1024
#define DMODEL  1024
#define DFF_    4096
#define NHEAD   16
#define DHEAD   64
#define ROWS    (BATCH * SEQ)      // 4096
#define ATT_SCALE 0.03125f         // 1/sqrt(1024)
#define LN_EPS  1e-5f

// ---------------------------------------------------------------------------
// Scratch buffers (device globals; no dynamic allocation allowed)
// ---------------------------------------------------------------------------
__device__ float g_q  [ROWS * DMODEL];
__device__ float g_k  [ROWS * DMODEL];
__device__ float g_v  [ROWS * DMODEL];
__device__ float g_att[ROWS * DMODEL];
__device__ float g_o  [ROWS * DMODEL];
__device__ float g_x  [ROWS * DMODEL];
__device__ float g_ff [ROWS * DFF_ ];
__device__ float g_y  [ROWS * DMODEL];

// ---------------------------------------------------------------------------
// SGEMM: C[M,N] = A[M,K] @ B[K,N] + bias[N], optional ReLU.
// 128x128 block tile, BK=8, 256 threads, 8x8 per-thread microtile.
// M,N,K all multiples of 128/8 here, so no bounds checks.
// ---------------------------------------------------------------------------
template<int RELU>
__global__ void __launch_bounds__(256)
sgemm_bias(const float* __restrict__ A, const float* __restrict__ B,
           const float* __restrict__ bias, float* __restrict__ C,
           int M, int N, int K)
{
    constexpr int BM = 128, BN = 128, BK = 8, TM = 8, TN = 8;
    __shared__ float As[BK][BM];
    __shared__ float Bs[BK][BN];

    const int tid  = threadIdx.x;
    const int crow = blockIdx.y * BM;
    const int ccol = blockIdx.x * BN;

    const float* Ap = A + (size_t)crow * K;
    const float* Bp = B + ccol;

    const int iA_r = tid >> 1;          // 0..127
    const int iA_c = (tid & 1) << 2;    // 0 or 4
    const int iB_r = tid >> 5;          // 0..7
    const int iB_c = (tid & 31) << 2;   // 0..124

    const int tr = (tid >> 4) * TM;
    const int tc = (tid & 15) * TN;

    float acc[TM][TN];
    #pragma unroll
    for (int i = 0; i < TM; i++)
        #pragma unroll
        for (int j = 0; j < TN; j++) acc[i][j] = 0.f;

    for (int k0 = 0; k0 < K; k0 += BK) {
        float4 a4 = *reinterpret_cast<const float4*>(Ap + (size_t)iA_r * K + k0 + iA_c);
        As[iA_c + 0][iA_r] = a4.x;
        As[iA_c + 1][iA_r] = a4.y;
        As[iA_c + 2][iA_r] = a4.z;
        As[iA_c + 3][iA_r] = a4.w;
        float4 b4 = *reinterpret_cast<const float4*>(Bp + (size_t)(k0 + iB_r) * N + iB_c);
        *reinterpret_cast<float4*>(&Bs[iB_r][iB_c]) = b4;
        __syncthreads();

        #pragma unroll
        for (int kk = 0; kk < BK; kk++) {
            float rm[TM], rn[TN];
            #pragma unroll
            for (int i = 0; i < TM; i++) rm[i] = As[kk][tr + i];
            #pragma unroll
            for (int j = 0; j < TN; j++) rn[j] = Bs[kk][tc + j];
            #pragma unroll
            for (int i = 0; i < TM; i++)
                #pragma unroll
                for (int j = 0; j < TN; j++)
                    acc[i][j] = fmaf(rm[i], rn[j], acc[i][j]);
        }
        __syncthreads();
    }

    #pragma unroll
    for (int i = 0; i < TM; i++) {
        float* Crow = C + (size_t)(crow + tr + i) * N + ccol + tc;
        #pragma unroll
        for (int j = 0; j < TN; j++) {
            float v = acc[i][j] + bias[ccol + tc + j];
            if (RELU) v = fmaxf(v, 0.f);
            Crow[j] = v;
        }
    }
}

// ---------------------------------------------------------------------------
// Flash attention (fp32, online softmax). One block per (q-tile of 64, b*h).
// 256 threads; each thread owns a 4x4 tile of the 64x64 score matrix.
// Dynamic smem: qs[64][65], ks[64][65] (reused for P), vs[64][65].
// ---------------------------------------------------------------------------
#define SIDX(r, c) ((r) * 65 + (c))
#define FLASH_SMEM (3 * 64 * 65 * (int)sizeof(float))

__global__ void __launch_bounds__(256)
flash_attn(const float* __restrict__ Q, const float* __restrict__ K,
           const float* __restrict__ V, float* __restrict__ O)
{
    extern __shared__ float sm[];
    float* qs = sm;
    float* ks = sm + 64 * 65;   // reused as P after scores are consumed
    float* vs = sm + 2 * 64 * 65;

    const int tid = threadIdx.x;
    const int qt  = blockIdx.x;        // 0..15
    const int b   = blockIdx.y >> 4;   // 0..3
    const int h   = blockIdx.y & 15;   // 0..15

    const size_t qoff = ((size_t)b * SEQ + qt * 64) * (size_t)DMODEL + h * DHEAD;
    const size_t koff = (size_t)b * SEQ * DMODEL + h * DHEAD;

    // load 64x64 q tile (coalesced along dh)
    for (int i = tid; i < 64 * 64; i += 256) {
        int r = i >> 6, c = i & 63;
        qs[SIDX(r, c)] = Q[qoff + (size_t)r * DMODEL + c];
    }

    const int tr = (tid >> 4) << 2;    // query rows owned by thread
    const int tc = (tid & 15) << 2;    // key cols / dh cols owned by thread

    float m[4] = {-1e30f, -1e30f, -1e30f, -1e30f};
    float l[4] = {0.f, 0.f, 0.f, 0.f};
    float o[4][4];
    #pragma unroll
    for (int i = 0; i < 4; i++)
        #pragma unroll
        for (int j = 0; j < 4; j++) o[i][j] = 0.f;

    __syncthreads();

    for (int kt = 0; kt < SEQ / 64; kt++) {
        // load k,v tiles for this key block
        for (int i = tid; i < 64 * 64; i += 256) {
            int r = i >> 6, c = i & 63;
            size_t gofs = koff + (size_t)(kt * 64 + r) * DMODEL + c;
            ks[SIDX(r, c)] = K[gofs];
            vs[SIDX(r, c)] = V[gofs];
        }
        __syncthreads();

        // S = q @ k^T  (per-thread 4x4)
        float s[4][4];
        #pragma unroll
        for (int i = 0; i < 4; i++)
            #pragma unroll
            for (int j = 0; j < 4; j++) s[i][j] = 0.f;

        #pragma unroll 8
        for (int kk = 0; kk < 64; kk++) {
            float rq[4], rk[4];
            #pragma unroll
            for (int i = 0; i < 4; i++) rq[i] = qs[SIDX(tr + i, kk)];
            #pragma unroll
            for (int j = 0; j < 4; j++) rk[j] = ks[SIDX(tc + j, kk)];
            #pragma unroll
            for (int i = 0; i < 4; i++)
                #pragma unroll
                for (int j = 0; j < 4; j++)
                    s[i][j] = fmaf(rq[i], rk[j], s[i][j]);
        }
        __syncthreads();   // everyone done reading ks -> safe to overwrite with P

        // online softmax update (row groups of 16 threads = half-warp shuffles)
        #pragma unroll
        for (int i = 0; i < 4; i++) {
            float mx = -1e30f;
            #pragma unroll
            for (int j = 0; j < 4; j++) {
                s[i][j] *= ATT_SCALE;
                mx = fmaxf(mx, s[i][j]);
            }
            #pragma unroll
            for (int off = 8; off; off >>= 1)
                mx = fmaxf(mx, __shfl_xor_sync(0xffffffffu, mx, off));
            float mn   = fmaxf(m[i], mx);
            float corr = __expf(m[i] - mn);
            m[i] = mn;
            float rs = 0.f;
            #pragma unroll
            for (int j = 0; j < 4; j++) {
                s[i][j] = __expf(s[i][j] - mn);
                rs += s[i][j];
            }
            #pragma unroll
            for (int off = 8; off; off >>= 1)
                rs += __shfl_xor_sync(0xffffffffu, rs, off);
            l[i] = l[i] * corr + rs;
            #pragma unroll
            for (int j = 0; j < 4; j++) o[i][j] *= corr;
            #pragma unroll
            for (int j = 0; j < 4; j++) ks[SIDX(tr + i, tc + j)] = s[i][j];
        }
        __syncthreads();   // P fully staged

        // O += P @ V
        #pragma unroll 8
        for (int kk = 0; kk < 64; kk++) {
            float rp[4], rv[4];
            #pragma unroll
            for (int i = 0; i < 4; i++) rp[i] = ks[SIDX(tr + i, kk)];
            #pragma unroll
            for (int j = 0; j < 4; j++) rv[j] = vs[SIDX(kk, tc + j)];
            #pragma unroll
            for (int i = 0; i < 4; i++)
                #pragma unroll
                for (int j = 0; j < 4; j++)
                    o[i][j] = fmaf(rp[i], rv[j], o[i][j]);
        }
        __syncthreads();   // done with ks/vs before next tile load
    }

    #pragma unroll
    for (int i = 0; i < 4; i++) {
        float inv = 1.f / l[i];
        size_t row = (size_t)b * SEQ + qt * 64 + tr + i;
        #pragma unroll
        for (int j = 0; j < 4; j++)
            O[row * DMODEL + h * DHEAD + tc + j] = o[i][j] * inv;
    }
}

// ---------------------------------------------------------------------------
// Fused residual add + LayerNorm: out[row] = LN(A[row] + R[row]) * g + be
// One 256-thread block per row of 1024.
// ---------------------------------------------------------------------------
__global__ void __launch_bounds__(256)
add_ln(const float* __restrict__ A, const float* __restrict__ R,
       const float* __restrict__ g, const float* __restrict__ be,
       float* __restrict__ out)
{
    const int row = blockIdx.x;
    const int tid = threadIdx.x;
    const size_t base = (size_t)row * DMODEL;

    float x[4];
    float sum = 0.f;
    #pragma unroll
    for (int i = 0; i < 4; i++) {
        int c = tid + i * 256;
        x[i] = A[base + c] + R[base + c];
        sum += x[i];
    }

    __shared__ float red[8];
    __shared__ float red2[8];
    #pragma unroll
    for (int off = 16; off; off >>= 1)
        sum += __shfl_xor_sync(0xffffffffu, sum, off);
    if ((tid & 31) == 0) red[tid >> 5] = sum;
    __syncthreads();
    float tot = 0.f;
    #pragma unroll
    for (int w = 0; w < 8; w++) tot += red[w];
    const float mean = tot * (1.f / (float)DMODEL);

    float vsum = 0.f;
    #pragma unroll
    for (int i = 0; i < 4; i++) {
        x[i] -= mean;
        vsum += x[i] * x[i];
    }
    #pragma unroll
    for (int off = 16; off; off >>= 1)
        vsum += __shfl_xor_sync(0xffffffffu, vsum, off);
    if ((tid & 31) == 0) red2[tid >> 5] = vsum;
    __syncthreads();
    float vtot = 0.f;
    #pragma unroll
    for (int w = 0; w < 8; w++) vtot += red2[w];
    const float rstd = rsqrtf(vtot * (1.f / (float)DMODEL) + LN_EPS);

    #pragma unroll
    for (int i = 0; i < 4; i++) {
        int c = tid + i * 256;
        out[base + c] = x[i] * rstd * g[c] + be[c];
    }
}

// ---------------------------------------------------------------------------
// Launch
// ---------------------------------------------------------------------------
extern "C" void kernel_launch(void* const* d_in, const int* in_sizes, int n_in,
                              void* d_out, int out_size)
{
    (void)in_sizes; (void)n_in; (void)out_size;

    const float* Q   = (const float*)d_in[0];
    const float* Kin = (const float*)d_in[1];
    const float* Wq  = (const float*)d_in[2];
    const float* bq  = (const float*)d_in[3];
    const float* Wk  = (const float*)d_in[4];
    const float* bk  = (const float*)d_in[5];
    const float* Wv  = (const float*)d_in[6];
    const float* bv  = (const float*)d_in[7];
    const float* Wo  = (const float*)d_in[8];
    const float* bo  = (const float*)d_in[9];
    const float* W1  = (const float*)d_in[10];
    const float* b1  = (const float*)d_in[11];
    const float* W2  = (const float*)d_in[12];
    const float* b2  = (const float*)d_in[13];
    const float* g0  = (const float*)d_in[14];
    const float* be0 = (const float*)d_in[15];
    const float* g1  = (const float*)d_in[16];
    const float* be1 = (const float*)d_in[17];
    float* out = (float*)d_out;

    float *pq, *pk, *pv, *patt, *po, *px, *pff, *py;
    cudaGetSymbolAddress((void**)&pq,   g_q);
    cudaGetSymbolAddress((void**)&pk,   g_k);
    cudaGetSymbolAddress((void**)&pv,   g_v);
    cudaGetSymbolAddress((void**)&patt, g_att);
    cudaGetSymbolAddress((void**)&po,   g_o);
    cudaGetSymbolAddress((void**)&px,   g_x);
    cudaGetSymbolAddress((void**)&pff,  g_ff);
    cudaGetSymbolAddress((void**)&py,   g_y);

    cudaFuncSetAttribute(flash_attn, cudaFuncAttributeMaxDynamicSharedMemorySize,
                         FLASH_SMEM);

    const dim3 blk(256);
    const dim3 gProj(DMODEL / 128, ROWS / 128);   // (8, 32)
    const dim3 gFF1 (DFF_   / 128, ROWS / 128);   // (32, 32)
    const dim3 gFF2 (DMODEL / 128, ROWS / 128);   // (8, 32)

    // QKV projections
    sgemm_bias<0><<<gProj, blk>>>(Q,   Wq, bq, pq, ROWS, DMODEL, DMODEL);
    sgemm_bias<0><<<gProj, blk>>>(Kin, Wk, bk, pk, ROWS, DMODEL, DMODEL);
    sgemm_bias<0><<<gProj, blk>>>(Kin, Wv, bv, pv, ROWS, DMODEL, DMODEL);

    // multi-head attention
    flash_attn<<<dim3(SEQ / 64, BATCH * NHEAD), blk, FLASH_SMEM>>>(pq, pk, pv, patt);

    // output projection + residual + LN0
    sgemm_bias<0><<<gProj, blk>>>(patt, Wo, bo, po, ROWS, DMODEL, DMODEL);
    add_ln<<<ROWS, 256>>>(po, Q, g0, be0, px);

    // FFN + residual + LN1
    sgemm_bias<1><<<gFF1, blk>>>(px,  W1, b1, pff, ROWS, DFF_,  DMODEL);
    sgemm_bias<0><<<gFF2, blk>>>(pff, W2, b2, py,  ROWS, DMODEL, DFF_);
    add_ln<<<ROWS, 256>>>(py, px, g1, be1, out);
}

// round 2
// speedup vs baseline: 2.3647x; 2.3647x over previous
#include <cuda_runtime.h>
#include <math.h>
#include <stdint.h>

// Problem constants
#define BATCH   4
#define SEQ     1024
#define DMODEL  1024
#define DFF_    4096
#define NHEAD   16
#define DHEAD   64
#define ROWS    (BATCH * SEQ)      // 4096
#define ATT_SCALE 0.03125f         // 1/sqrt(1024)
#define LN_EPS  1e-5f

// ---------------------------------------------------------------------------
// Scratch buffers (device globals; no dynamic allocation allowed)
// ---------------------------------------------------------------------------
__device__ float g_q  [ROWS * DMODEL];
__device__ float g_k  [ROWS * DMODEL];
__device__ float g_v  [ROWS * DMODEL];
__device__ float g_att[ROWS * DMODEL];
__device__ float g_o  [ROWS * DMODEL];
__device__ float g_x  [ROWS * DMODEL];
__device__ float g_ff [ROWS * DFF_ ];
__device__ float g_y  [ROWS * DMODEL];

// ---------------------------------------------------------------------------
// tf32 tensor-core GEMM: C[M,N] = A[M,K] @ B[K,N] + bias[N], optional ReLU.
// 128x128 block tile, BK=16, 256 threads (8 warps, 64x32 warp tiles),
// mma.sync.m16n8k8.tf32, cp.async double-buffered smem.
// blockIdx.z selects among up to 3 independent (A,B,bias,C) problem instances
// (used to batch the QKV projections into one launch).
// ---------------------------------------------------------------------------
struct GemmBatch {
    const float* A[3];
    const float* B[3];
    const float* bias[3];
    float*       C[3];
};

#define BM 128
#define BN 128
#define BKT 16
#define AS_STRIDE 20     // 16 + 4 pad (keeps 16B alignment, kills bank conflicts)
#define BS_STRIDE 136    // 128 + 8 pad

__device__ __forceinline__ void cp_async16(uint32_t s, const void* g) {
    asm volatile("cp.async.cg.shared.global [%0], [%1], 16;\n" :: "r"(s), "l"(g));
}
__device__ __forceinline__ uint32_t f2tf32(float f) {
    uint32_t u;
    asm("cvt.rna.tf32.f32 %0, %1;" : "=r"(u) : "f"(f));
    return u;
}

template<int RELU>
__global__ void __launch_bounds__(256, 2)
gemm_tf32(GemmBatch gb, int M, int N, int K)
{
    const int z = blockIdx.z;
    const float* __restrict__ A    = gb.A[z];
    const float* __restrict__ B    = gb.B[z];
    const float* __restrict__ bias = gb.bias[z];
    float*       __restrict__ C    = gb.C[z];

    __shared__ float As[2][BM * AS_STRIDE];
    __shared__ float Bs[2][BKT * BS_STRIDE];

    const int tid  = threadIdx.x;
    const int lane = tid & 31;
    const int warp = tid >> 5;
    const int wm   = (warp >> 2) * 64;   // warp m offset within block tile
    const int wn   = (warp & 3) * 32;    // warp n offset

    const int crow = blockIdx.y * BM;
    const int ccol = blockIdx.x * BN;

    const float* Ap = A + (size_t)crow * K;
    const float* Bp = B + ccol;

    // global->smem mapping (2 x 16B per thread for each of A,B per stage)
    const int a_row0 = tid >> 2;               // 0..63  (+64 for second chunk)
    const int a_col  = (tid & 3) << 2;         // 0,4,8,12
    const int b_row0 = tid >> 5;               // 0..7   (+8)
    const int b_col  = (tid & 31) << 2;        // 0..124

    uint32_t as_base = (uint32_t)__cvta_generic_to_shared(&As[0][0]);
    uint32_t bs_base = (uint32_t)__cvta_generic_to_shared(&Bs[0][0]);

    const int NIT = K / BKT;

    auto load_stage = [&](int st, int k0) {
        uint32_t as = as_base + st * (BM * AS_STRIDE * 4);
        uint32_t bs = bs_base + st * (BKT * BS_STRIDE * 4);
        #pragma unroll
        for (int i = 0; i < 2; i++) {
            int ar = a_row0 + i * 64;
            cp_async16(as + (ar * AS_STRIDE + a_col) * 4,
                       Ap + (size_t)ar * K + k0 + a_col);
            int br = b_row0 + i * 8;
            cp_async16(bs + (br * BS_STRIDE + b_col) * 4,
                       Bp + (size_t)(k0 + br) * N + b_col);
        }
        asm volatile("cp.async.commit_group;\n");
    };

    float acc[4][4][4];
    #pragma unroll
    for (int mi = 0; mi < 4; mi++)
        #pragma unroll
        for (int ni = 0; ni < 4; ni++)
            #pragma unroll
            for (int r = 0; r < 4; r++) acc[mi][ni][r] = 0.f;

    const int fr = lane >> 2;    // 0..7
    const int fc = lane & 3;     // 0..3

    load_stage(0, 0);

    for (int it = 0; it < NIT; it++) {
        const int cur = it & 1;
        if (it + 1 < NIT) {
            load_stage(cur ^ 1, (it + 1) * BKT);
            asm volatile("cp.async.wait_group 1;\n");
        } else {
            asm volatile("cp.async.wait_group 0;\n");
        }
        __syncthreads();

        const float* as = &As[cur][0];
        const float* bs = &Bs[cur][0];

        #pragma unroll
        for (int ks = 0; ks < 2; ks++) {
            const int kb = ks * 8;
            uint32_t af[4][4];
            uint32_t bf[4][2];
            #pragma unroll
            for (int mi = 0; mi < 4; mi++) {
                const float* a = as + (wm + mi * 16 + fr) * AS_STRIDE + kb + fc;
                af[mi][0] = f2tf32(a[0]);
                af[mi][1] = f2tf32(a[8 * AS_STRIDE]);
                af[mi][2] = f2tf32(a[4]);
                af[mi][3] = f2tf32(a[8 * AS_STRIDE + 4]);
            }
            #pragma unroll
            for (int ni = 0; ni < 4; ni++) {
                const float* b = bs + (kb + fc) * BS_STRIDE + wn + ni * 8 + fr;
                bf[ni][0] = f2tf32(b[0]);
                bf[ni][1] = f2tf32(b[4 * BS_STRIDE]);
            }
            #pragma unroll
            for (int mi = 0; mi < 4; mi++)
                #pragma unroll
                for (int ni = 0; ni < 4; ni++) {
                    asm volatile(
                        "mma.sync.aligned.m16n8k8.row.col.f32.tf32.tf32.f32 "
                        "{%0,%1,%2,%3}, {%4,%5,%6,%7}, {%8,%9}, {%0,%1,%2,%3};\n"
                        : "+f"(acc[mi][ni][0]), "+f"(acc[mi][ni][1]),
                          "+f"(acc[mi][ni][2]), "+f"(acc[mi][ni][3])
                        : "r"(af[mi][0]), "r"(af[mi][1]), "r"(af[mi][2]), "r"(af[mi][3]),
                          "r"(bf[ni][0]), "r"(bf[ni][1]));
                }
        }
        __syncthreads();
    }

    // epilogue: bias (+ optional relu), float2 stores
    #pragma unroll
    for (int mi = 0; mi < 4; mi++) {
        #pragma unroll
        for (int ni = 0; ni < 4; ni++) {
            const int row = crow + wm + mi * 16 + fr;
            const int col = ccol + wn + ni * 8 + 2 * fc;
            float b0 = bias[col], b1 = bias[col + 1];
            float2 v0 = make_float2(acc[mi][ni][0] + b0, acc[mi][ni][1] + b1);
            float2 v1 = make_float2(acc[mi][ni][2] + b0, acc[mi][ni][3] + b1);
            if (RELU) {
                v0.x = fmaxf(v0.x, 0.f); v0.y = fmaxf(v0.y, 0.f);
                v1.x = fmaxf(v1.x, 0.f); v1.y = fmaxf(v1.y, 0.f);
            }
            *reinterpret_cast<float2*>(C + (size_t)row * N + col)       = v0;
            *reinterpret_cast<float2*>(C + (size_t)(row + 8) * N + col) = v1;
        }
    }
}

// ---------------------------------------------------------------------------
// Flash attention (fp32, online softmax). One block per (q-tile of 64, b*h).
// ---------------------------------------------------------------------------
#define SIDX(r, c) ((r) * 65 + (c))
#define FLASH_SMEM (3 * 64 * 65 * (int)sizeof(float))

__global__ void __launch_bounds__(256)
flash_attn(const float* __restrict__ Q, const float* __restrict__ K,
           const float* __restrict__ V, float* __restrict__ O)
{
    extern __shared__ float sm[];
    float* qs = sm;
    float* ks = sm + 64 * 65;   // reused as P after scores are consumed
    float* vs = sm + 2 * 64 * 65;

    const int tid = threadIdx.x;
    const int qt  = blockIdx.x;
    const int b   = blockIdx.y >> 4;
    const int h   = blockIdx.y & 15;

    const size_t qoff = ((size_t)b * SEQ + qt * 64) * (size_t)DMODEL + h * DHEAD;
    const size_t koff = (size_t)b * SEQ * DMODEL + h * DHEAD;

    for (int i = tid; i < 64 * 64; i += 256) {
        int r = i >> 6, c = i & 63;
        qs[SIDX(r, c)] = Q[qoff + (size_t)r * DMODEL + c];
    }

    const int tr = (tid >> 4) << 2;
    const int tc = (tid & 15) << 2;

    float m[4] = {-1e30f, -1e30f, -1e30f, -1e30f};
    float l[4] = {0.f, 0.f, 0.f, 0.f};
    float o[4][4];
    #pragma unroll
    for (int i = 0; i < 4; i++)
        #pragma unroll
        for (int j = 0; j < 4; j++) o[i][j] = 0.f;

    __syncthreads();

    for (int kt = 0; kt < SEQ / 64; kt++) {
        for (int i = tid; i < 64 * 64; i += 256) {
            int r = i >> 6, c = i & 63;
            size_t gofs = koff + (size_t)(kt * 64 + r) * DMODEL + c;
            ks[SIDX(r, c)] = K[gofs];
            vs[SIDX(r, c)] = V[gofs];
        }
        __syncthreads();

        float s[4][4];
        #pragma unroll
        for (int i = 0; i < 4; i++)
            #pragma unroll
            for (int j = 0; j < 4; j++) s[i][j] = 0.f;

        #pragma unroll 8
        for (int kk = 0; kk < 64; kk++) {
            float rq[4], rk[4];
            #pragma unroll
            for (int i = 0; i < 4; i++) rq[i] = qs[SIDX(tr + i, kk)];
            #pragma unroll
            for (int j = 0; j < 4; j++) rk[j] = ks[SIDX(tc + j, kk)];
            #pragma unroll
            for (int i = 0; i < 4; i++)
                #pragma unroll
                for (int j = 0; j < 4; j++)
                    s[i][j] = fmaf(rq[i], rk[j], s[i][j]);
        }
        __syncthreads();

        #pragma unroll
        for (int i = 0; i < 4; i++) {
            float mx = -1e30f;
            #pragma unroll
            for (int j = 0; j < 4; j++) {
                s[i][j] *= ATT_SCALE;
                mx = fmaxf(mx, s[i][j]);
            }
            #pragma unroll
            for (int off = 8; off; off >>= 1)
                mx = fmaxf(mx, __shfl_xor_sync(0xffffffffu, mx, off));
            float mn   = fmaxf(m[i], mx);
            float corr = __expf(m[i] - mn);
            m[i] = mn;
            float rs = 0.f;
            #pragma unroll
            for (int j = 0; j < 4; j++) {
                s[i][j] = __expf(s[i][j] - mn);
                rs += s[i][j];
            }
            #pragma unroll
            for (int off = 8; off; off >>= 1)
                rs += __shfl_xor_sync(0xffffffffu, rs, off);
            l[i] = l[i] * corr + rs;
            #pragma unroll
            for (int j = 0; j < 4; j++) o[i][j] *= corr;
            #pragma unroll
            for (int j = 0; j < 4; j++) ks[SIDX(tr + i, tc + j)] = s[i][j];
        }
        __syncthreads();

        #pragma unroll 8
        for (int kk = 0; kk < 64; kk++) {
            float rp[4], rv[4];
            #pragma unroll
            for (int i = 0; i < 4; i++) rp[i] = ks[SIDX(tr + i, kk)];
            #pragma unroll
            for (int j = 0; j < 4; j++) rv[j] = vs[SIDX(kk, tc + j)];
            #pragma unroll
            for (int i = 0; i < 4; i++)
                #pragma unroll
                for (int j = 0; j < 4; j++)
                    o[i][j] = fmaf(rp[i], rv[j], o[i][j]);
        }
        __syncthreads();
    }

    #pragma unroll
    for (int i = 0; i < 4; i++) {
        float inv = 1.f / l[i];
        size_t row = (size_t)b * SEQ + qt * 64 + tr + i;
        #pragma unroll
        for (int j = 0; j < 4; j++)
            O[row * DMODEL + h * DHEAD + tc + j] = o[i][j] * inv;
    }
}

// ---------------------------------------------------------------------------
// Fused residual add + LayerNorm
// ---------------------------------------------------------------------------
__global__ void __launch_bounds__(256)
add_ln(const float* __restrict__ A, const float* __restrict__ R,
       const float* __restrict__ g, const float* __restrict__ be,
       float* __restrict__ out)
{
    const int row = blockIdx.x;
    const int tid = threadIdx.x;
    const size_t base = (size_t)row * DMODEL;

    float x[4];
    float sum = 0.f;
    #pragma unroll
    for (int i = 0; i < 4; i++) {
        int c = tid + i * 256;
        x[i] = A[base + c] + R[base + c];
        sum += x[i];
    }

    __shared__ float red[8];
    __shared__ float red2[8];
    #pragma unroll
    for (int off = 16; off; off >>= 1)
        sum += __shfl_xor_sync(0xffffffffu, sum, off);
    if ((tid & 31) == 0) red[tid >> 5] = sum;
    __syncthreads();
    float tot = 0.f;
    #pragma unroll
    for (int w = 0; w < 8; w++) tot += red[w];
    const float mean = tot * (1.f / (float)DMODEL);

    float vsum = 0.f;
    #pragma unroll
    for (int i = 0; i < 4; i++) {
        x[i] -= mean;
        vsum += x[i] * x[i];
    }
    #pragma unroll
    for (int off = 16; off; off >>= 1)
        vsum += __shfl_xor_sync(0xffffffffu, vsum, off);
    if ((tid & 31) == 0) red2[tid >> 5] = vsum;
    __syncthreads();
    float vtot = 0.f;
    #pragma unroll
    for (int w = 0; w < 8; w++) vtot += red2[w];
    const float rstd = rsqrtf(vtot * (1.f / (float)DMODEL) + LN_EPS);

    #pragma unroll
    for (int i = 0; i < 4; i++) {
        int c = tid + i * 256;
        out[base + c] = x[i] * rstd * g[c] + be[c];
    }
}

// ---------------------------------------------------------------------------
// Launch
// ---------------------------------------------------------------------------
extern "C" void kernel_launch(void* const* d_in, const int* in_sizes, int n_in,
                              void* d_out, int out_size)
{
    (void)in_sizes; (void)n_in; (void)out_size;

    const float* Q   = (const float*)d_in[0];
    const float* Kin = (const float*)d_in[1];
    const float* Wq  = (const float*)d_in[2];
    const float* bq  = (const float*)d_in[3];
    const float* Wk  = (const float*)d_in[4];
    const float* bk  = (const float*)d_in[5];
    const float* Wv  = (const float*)d_in[6];
    const float* bv  = (const float*)d_in[7];
    const float* Wo  = (const float*)d_in[8];
    const float* bo  = (const float*)d_in[9];
    const float* W1  = (const float*)d_in[10];
    const float* b1  = (const float*)d_in[11];
    const float* W2  = (const float*)d_in[12];
    const float* b2  = (const float*)d_in[13];
    const float* g0  = (const float*)d_in[14];
    const float* be0 = (const float*)d_in[15];
    const float* g1  = (const float*)d_in[16];
    const float* be1 = (const float*)d_in[17];
    float* out = (float*)d_out;

    float *pq, *pk, *pv, *patt, *po, *px, *pff, *py;
    cudaGetSymbolAddress((void**)&pq,   g_q);
    cudaGetSymbolAddress((void**)&pk,   g_k);
    cudaGetSymbolAddress((void**)&pv,   g_v);
    cudaGetSymbolAddress((void**)&patt, g_att);
    cudaGetSymbolAddress((void**)&po,   g_o);
    cudaGetSymbolAddress((void**)&px,   g_x);
    cudaGetSymbolAddress((void**)&pff,  g_ff);
    cudaGetSymbolAddress((void**)&py,   g_y);

    cudaFuncSetAttribute(flash_attn, cudaFuncAttributeMaxDynamicSharedMemorySize,
                         FLASH_SMEM);

    const dim3 blk(256);

    // QKV projections in one batched launch (fills the chip: 768 CTAs)
    {
        GemmBatch gb;
        gb.A[0] = Q;   gb.B[0] = Wq; gb.bias[0] = bq; gb.C[0] = pq;
        gb.A[1] = Kin; gb.B[1] = Wk; gb.bias[1] = bk; gb.C[1] = pk;
        gb.A[2] = Kin; gb.B[2] = Wv; gb.bias[2] = bv; gb.C[2] = pv;
        dim3 g(DMODEL / BN, ROWS / BM, 3);
        gemm_tf32<0><<<g, blk>>>(gb, ROWS, DMODEL, DMODEL);
    }

    // multi-head attention
    flash_attn<<<dim3(SEQ / 64, BATCH * NHEAD), blk, FLASH_SMEM>>>(pq, pk, pv, patt);

    // output projection + residual + LN0
    {
        GemmBatch gb;
        gb.A[0] = patt; gb.B[0] = Wo; gb.bias[0] = bo; gb.C[0] = po;
        dim3 g(DMODEL / BN, ROWS / BM, 1);
        gemm_tf32<0><<<g, blk>>>(gb, ROWS, DMODEL, DMODEL);
    }
    add_ln<<<ROWS, 256>>>(po, Q, g0, be0, px);

    // FFN + residual + LN1
    {
        GemmBatch gb;
        gb.A[0] = px; gb.B[0] = W1; gb.bias[0] = b1; gb.C[0] = pff;
        dim3 g(DFF_ / BN, ROWS / BM, 1);
        gemm_tf32<1><<<g, blk>>>(gb, ROWS, DFF_, DMODEL);
    }
    {
        GemmBatch gb;
        gb.A[0] = pff; gb.B[0] = W2; gb.bias[0] = b2; gb.C[0] = py;
        dim3 g(DMODEL / BN, ROWS / BM, 1);
        gemm_tf32<0><<<g, blk>>>(gb, ROWS, DMODEL, DFF_);
    }
    add_ln<<<ROWS, 256>>>(py, px, g1, be1, out);
}

// round 3
// speedup vs baseline: 2.8261x; 1.1951x over previous
#include <cuda_runtime.h>
#include <math.h>
#include <stdint.h>

// Problem constants
#define BATCH   4
#define SEQ     1024
#define DMODEL  1024
#define DFF_    4096
#define NHEAD   16
#define DHEAD   64
#define ROWS    (BATCH * SEQ)      // 4096
#define ATT_SCALE 0.03125f         // 1/sqrt(1024)
#define LN_EPS  1e-5f

// ---------------------------------------------------------------------------
// Scratch buffers (device globals; no dynamic allocation allowed)
// ---------------------------------------------------------------------------
__device__ float g_q  [ROWS * DMODEL];
__device__ float g_k  [ROWS * DMODEL];
__device__ float g_v  [ROWS * DMODEL];
__device__ float g_att[ROWS * DMODEL];
__device__ float g_o  [ROWS * DMODEL];
__device__ float g_x  [ROWS * DMODEL];
__device__ float g_ff [ROWS * DFF_ ];
__device__ float g_y  [ROWS * DMODEL];

__device__ __forceinline__ void cp_async16(uint32_t s, const void* g) {
    asm volatile("cp.async.cg.shared.global [%0], [%1], 16;\n" :: "r"(s), "l"(g));
}
__device__ __forceinline__ uint32_t f2tf32(float f) {
    uint32_t u;
    asm("cvt.rna.tf32.f32 %0, %1;" : "=r"(u) : "f"(f));
    return u;
}
__device__ __forceinline__ float f2tf32f(float f) {
    return __uint_as_float(f2tf32(f));
}
__device__ __forceinline__ void mma_tf32(float* c, uint32_t a0, uint32_t a1,
                                         uint32_t a2, uint32_t a3,
                                         uint32_t b0, uint32_t b1) {
    asm volatile(
        "mma.sync.aligned.m16n8k8.row.col.f32.tf32.tf32.f32 "
        "{%0,%1,%2,%3}, {%4,%5,%6,%7}, {%8,%9}, {%0,%1,%2,%3};\n"
        : "+f"(c[0]), "+f"(c[1]), "+f"(c[2]), "+f"(c[3])
        : "r"(a0), "r"(a1), "r"(a2), "r"(a3), "r"(b0), "r"(b1));
}

// ---------------------------------------------------------------------------
// tf32 tensor-core GEMM: C[M,N] = A[M,K] @ B[K,N] + bias[N], optional ReLU.
// 128x128 block tile, BK=16, 256 threads (8 warps, 64x32 warp tiles),
// mma.sync.m16n8k8.tf32, cp.async double-buffered smem.
// ---------------------------------------------------------------------------
struct GemmBatch {
    const float* A[3];
    const float* B[3];
    const float* bias[3];
    float*       C[3];
};

#define BM 128
#define BN 128
#define BKT 16
#define AS_STRIDE 20
#define BS_STRIDE 136

template<int RELU>
__global__ void __launch_bounds__(256, 2)
gemm_tf32(GemmBatch gb, int M, int N, int K)
{
    const int z = blockIdx.z;
    const float* __restrict__ A    = gb.A[z];
    const float* __restrict__ B    = gb.B[z];
    const float* __restrict__ bias = gb.bias[z];
    float*       __restrict__ C    = gb.C[z];

    __shared__ float As[2][BM * AS_STRIDE];
    __shared__ float Bs[2][BKT * BS_STRIDE];

    const int tid  = threadIdx.x;
    const int lane = tid & 31;
    const int warp = tid >> 5;
    const int wm   = (warp >> 2) * 64;
    const int wn   = (warp & 3) * 32;

    const int crow = blockIdx.y * BM;
    const int ccol = blockIdx.x * BN;

    const float* Ap = A + (size_t)crow * K;
    const float* Bp = B + ccol;

    const int a_row0 = tid >> 2;
    const int a_col  = (tid & 3) << 2;
    const int b_row0 = tid >> 5;
    const int b_col  = (tid & 31) << 2;

    uint32_t as_base = (uint32_t)__cvta_generic_to_shared(&As[0][0]);
    uint32_t bs_base = (uint32_t)__cvta_generic_to_shared(&Bs[0][0]);

    const int NIT = K / BKT;

    auto load_stage = [&](int st, int k0) {
        uint32_t as = as_base + st * (BM * AS_STRIDE * 4);
        uint32_t bs = bs_base + st * (BKT * BS_STRIDE * 4);
        #pragma unroll
        for (int i = 0; i < 2; i++) {
            int ar = a_row0 + i * 64;
            cp_async16(as + (ar * AS_STRIDE + a_col) * 4,
                       Ap + (size_t)ar * K + k0 + a_col);
            int br = b_row0 + i * 8;
            cp_async16(bs + (br * BS_STRIDE + b_col) * 4,
                       Bp + (size_t)(k0 + br) * N + b_col);
        }
        asm volatile("cp.async.commit_group;\n");
    };

    float acc[4][4][4];
    #pragma unroll
    for (int mi = 0; mi < 4; mi++)
        #pragma unroll
        for (int ni = 0; ni < 4; ni++)
            #pragma unroll
            for (int r = 0; r < 4; r++) acc[mi][ni][r] = 0.f;

    const int fr = lane >> 2;
    const int fc = lane & 3;

    load_stage(0, 0);

    for (int it = 0; it < NIT; it++) {
        const int cur = it & 1;
        if (it + 1 < NIT) {
            load_stage(cur ^ 1, (it + 1) * BKT);
            asm volatile("cp.async.wait_group 1;\n");
        } else {
            asm volatile("cp.async.wait_group 0;\n");
        }
        __syncthreads();

        const float* as = &As[cur][0];
        const float* bs = &Bs[cur][0];

        #pragma unroll
        for (int ks = 0; ks < 2; ks++) {
            const int kb = ks * 8;
            uint32_t af[4][4];
            uint32_t bf[4][2];
            #pragma unroll
            for (int mi = 0; mi < 4; mi++) {
                const float* a = as + (wm + mi * 16 + fr) * AS_STRIDE + kb + fc;
                af[mi][0] = f2tf32(a[0]);
                af[mi][1] = f2tf32(a[8 * AS_STRIDE]);
                af[mi][2] = f2tf32(a[4]);
                af[mi][3] = f2tf32(a[8 * AS_STRIDE + 4]);
            }
            #pragma unroll
            for (int ni = 0; ni < 4; ni++) {
                const float* b = bs + (kb + fc) * BS_STRIDE + wn + ni * 8 + fr;
                bf[ni][0] = f2tf32(b[0]);
                bf[ni][1] = f2tf32(b[4 * BS_STRIDE]);
            }
            #pragma unroll
            for (int mi = 0; mi < 4; mi++)
                #pragma unroll
                for (int ni = 0; ni < 4; ni++)
                    mma_tf32(acc[mi][ni], af[mi][0], af[mi][1], af[mi][2], af[mi][3],
                             bf[ni][0], bf[ni][1]);
        }
        __syncthreads();
    }

    #pragma unroll
    for (int mi = 0; mi < 4; mi++) {
        #pragma unroll
        for (int ni = 0; ni < 4; ni++) {
            const int row = crow + wm + mi * 16 + fr;
            const int col = ccol + wn + ni * 8 + 2 * fc;
            float b0 = bias[col], b1 = bias[col + 1];
            float2 v0 = make_float2(acc[mi][ni][0] + b0, acc[mi][ni][1] + b1);
            float2 v1 = make_float2(acc[mi][ni][2] + b0, acc[mi][ni][3] + b1);
            if (RELU) {
                v0.x = fmaxf(v0.x, 0.f); v0.y = fmaxf(v0.y, 0.f);
                v1.x = fmaxf(v1.x, 0.f); v1.y = fmaxf(v1.y, 0.f);
            }
            *reinterpret_cast<float2*>(C + (size_t)row * N + col)       = v0;
            *reinterpret_cast<float2*>(C + (size_t)(row + 8) * N + col) = v1;
        }
    }
}

// ---------------------------------------------------------------------------
// Tensor-core flash attention (tf32 mma, online softmax).
// 128 threads (4 warps); each warp owns 16 query rows. Q tile = 64 rows.
// K/V tiles of 64 keys staged in smem as tf32. P goes through per-warp smem.
// Strides: 68 (row-pattern loads, ≡4 mod 32) / 76 (dual-pattern, ≡12 mod 32)
// -> conflict-free fragment loads for all four access patterns.
// ---------------------------------------------------------------------------
#define SK_A 68
#define SK_B 76
#define FLASH_SMEM_TC ((2 * 64 * SK_A + 2 * 64 * SK_B) * (int)sizeof(float))

__global__ void __launch_bounds__(128)
flash_attn_tc(const float* __restrict__ Q, const float* __restrict__ K,
              const float* __restrict__ V, float* __restrict__ O)
{
    extern __shared__ float sm[];
    float* qs = sm;                          // [64][SK_A] tf32
    float* ps = sm + 64 * SK_A;              // [64][SK_A] tf32 (per-warp rows)
    float* ks = sm + 2 * 64 * SK_A;          // [64][SK_B] tf32  (layout [key][dh])
    float* vs = ks + 64 * SK_B;              // [64][SK_B] tf32  (layout [key][dh])

    const int tid  = threadIdx.x;
    const int lane = tid & 31;
    const int w    = tid >> 5;       // 0..3
    const int fr   = lane >> 2;      // 0..7
    const int fc   = lane & 3;       // 0..3

    const int qt = blockIdx.x;       // 0..15
    const int b  = blockIdx.y >> 4;
    const int h  = blockIdx.y & 15;

    const size_t qoff = ((size_t)b * SEQ + qt * 64) * (size_t)DMODEL + h * DHEAD;
    const size_t koff = (size_t)b * SEQ * DMODEL + h * DHEAD;

    // load + convert Q tile
    for (int i = tid; i < 64 * 64; i += 128) {
        int r = i >> 6, c = i & 63;
        qs[r * SK_A + c] = f2tf32f(Q[qoff + (size_t)r * DMODEL + c]);
    }

    float m0 = -1e30f, m1 = -1e30f;
    float l0 = 0.f, l1 = 0.f;
    float oacc[8][4];
    #pragma unroll
    for (int ni = 0; ni < 8; ni++)
        #pragma unroll
        for (int r = 0; r < 4; r++) oacc[ni][r] = 0.f;

    const int qrow = w * 16;          // warp's row base within tile

    for (int kt = 0; kt < SEQ / 64; kt++) {
        __syncthreads();   // previous tile's reads done (covers initial Q load)
        for (int i = tid; i < 64 * 64; i += 128) {
            int r = i >> 6, c = i & 63;
            size_t gofs = koff + (size_t)(kt * 64 + r) * DMODEL + c;
            ks[r * SK_B + c] = f2tf32f(K[gofs]);
            vs[r * SK_B + c] = f2tf32f(V[gofs]);
        }
        __syncthreads();

        // ---- S = Q @ K^T : per warp m16 x n64, k=64 ----
        float sacc[8][4];
        #pragma unroll
        for (int ni = 0; ni < 8; ni++)
            #pragma unroll
            for (int r = 0; r < 4; r++) sacc[ni][r] = 0.f;

        #pragma unroll
        for (int k8 = 0; k8 < 8; k8++) {
            const int kb = k8 * 8;
            const float* a = qs + (qrow + fr) * SK_A + kb + fc;
            uint32_t a0 = __float_as_uint(a[0]);
            uint32_t a1 = __float_as_uint(a[8 * SK_A]);
            uint32_t a2 = __float_as_uint(a[4]);
            uint32_t a3 = __float_as_uint(a[8 * SK_A + 4]);
            #pragma unroll
            for (int ni = 0; ni < 8; ni++) {
                const float* bp = ks + (ni * 8 + fr) * SK_B + kb + fc;
                uint32_t b0 = __float_as_uint(bp[0]);
                uint32_t b1 = __float_as_uint(bp[4]);
                mma_tf32(sacc[ni], a0, a1, a2, a3, b0, b1);
            }
        }

        // ---- online softmax on C fragments ----
        float mx0 = -1e30f, mx1 = -1e30f;
        #pragma unroll
        for (int ni = 0; ni < 8; ni++) {
            sacc[ni][0] *= ATT_SCALE; sacc[ni][1] *= ATT_SCALE;
            sacc[ni][2] *= ATT_SCALE; sacc[ni][3] *= ATT_SCALE;
            mx0 = fmaxf(mx0, fmaxf(sacc[ni][0], sacc[ni][1]));
            mx1 = fmaxf(mx1, fmaxf(sacc[ni][2], sacc[ni][3]));
        }
        mx0 = fmaxf(mx0, __shfl_xor_sync(0xffffffffu, mx0, 1));
        mx0 = fmaxf(mx0, __shfl_xor_sync(0xffffffffu, mx0, 2));
        mx1 = fmaxf(mx1, __shfl_xor_sync(0xffffffffu, mx1, 1));
        mx1 = fmaxf(mx1, __shfl_xor_sync(0xffffffffu, mx1, 2));

        float mn0 = fmaxf(m0, mx0), mn1 = fmaxf(m1, mx1);
        float corr0 = __expf(m0 - mn0), corr1 = __expf(m1 - mn1);
        m0 = mn0; m1 = mn1;

        float rs0 = 0.f, rs1 = 0.f;
        #pragma unroll
        for (int ni = 0; ni < 8; ni++) {
            sacc[ni][0] = __expf(sacc[ni][0] - mn0);
            sacc[ni][1] = __expf(sacc[ni][1] - mn0);
            sacc[ni][2] = __expf(sacc[ni][2] - mn1);
            sacc[ni][3] = __expf(sacc[ni][3] - mn1);
            rs0 += sacc[ni][0] + sacc[ni][1];
            rs1 += sacc[ni][2] + sacc[ni][3];
        }
        rs0 += __shfl_xor_sync(0xffffffffu, rs0, 1);
        rs0 += __shfl_xor_sync(0xffffffffu, rs0, 2);
        rs1 += __shfl_xor_sync(0xffffffffu, rs1, 1);
        rs1 += __shfl_xor_sync(0xffffffffu, rs1, 2);
        l0 = l0 * corr0 + rs0;
        l1 = l1 * corr1 + rs1;

        #pragma unroll
        for (int ni = 0; ni < 8; ni++) {
            oacc[ni][0] *= corr0; oacc[ni][1] *= corr0;
            oacc[ni][2] *= corr1; oacc[ni][3] *= corr1;
        }

        // stage P (tf32) in per-warp smem region
        #pragma unroll
        for (int ni = 0; ni < 8; ni++) {
            float* p = ps + (qrow + fr) * SK_A + ni * 8 + 2 * fc;
            p[0]             = f2tf32f(sacc[ni][0]);
            p[1]             = f2tf32f(sacc[ni][1]);
            p[8 * SK_A]      = f2tf32f(sacc[ni][2]);
            p[8 * SK_A + 1]  = f2tf32f(sacc[ni][3]);
        }
        __syncwarp();

        // ---- O += P @ V : per warp m16 x n64, k=64 ----
        #pragma unroll
        for (int k8 = 0; k8 < 8; k8++) {
            const int kb = k8 * 8;
            const float* a = ps + (qrow + fr) * SK_A + kb + fc;
            uint32_t a0 = __float_as_uint(a[0]);
            uint32_t a1 = __float_as_uint(a[8 * SK_A]);
            uint32_t a2 = __float_as_uint(a[4]);
            uint32_t a3 = __float_as_uint(a[8 * SK_A + 4]);
            #pragma unroll
            for (int ni = 0; ni < 8; ni++) {
                const float* bp = vs + (kb + fc) * SK_B + ni * 8 + fr;
                uint32_t b0 = __float_as_uint(bp[0]);
                uint32_t b1 = __float_as_uint(bp[4 * SK_B]);
                mma_tf32(oacc[ni], a0, a1, a2, a3, b0, b1);
            }
        }
    }

    // epilogue: normalize and store
    const float inv0 = 1.f / l0;
    const float inv1 = 1.f / l1;
    const size_t row0 = (size_t)b * SEQ + qt * 64 + qrow + fr;
    const size_t row1 = row0 + 8;
    #pragma unroll
    for (int ni = 0; ni < 8; ni++) {
        const int col = h * DHEAD + ni * 8 + 2 * fc;
        *reinterpret_cast<float2*>(O + row0 * DMODEL + col) =
            make_float2(oacc[ni][0] * inv0, oacc[ni][1] * inv0);
        *reinterpret_cast<float2*>(O + row1 * DMODEL + col) =
            make_float2(oacc[ni][2] * inv1, oacc[ni][3] * inv1);
    }
}

// ---------------------------------------------------------------------------
// Fused residual add + LayerNorm
// ---------------------------------------------------------------------------
__global__ void __launch_bounds__(256)
add_ln(const float* __restrict__ A, const float* __restrict__ R,
       const float* __restrict__ g, const float* __restrict__ be,
       float* __restrict__ out)
{
    const int row = blockIdx.x;
    const int tid = threadIdx.x;
    const size_t base = (size_t)row * DMODEL;

    float x[4];
    float sum = 0.f;
    #pragma unroll
    for (int i = 0; i < 4; i++) {
        int c = tid + i * 256;
        x[i] = A[base + c] + R[base + c];
        sum += x[i];
    }

    __shared__ float red[8];
    __shared__ float red2[8];
    #pragma unroll
    for (int off = 16; off; off >>= 1)
        sum += __shfl_xor_sync(0xffffffffu, sum, off);
    if ((tid & 31) == 0) red[tid >> 5] = sum;
    __syncthreads();
    float tot = 0.f;
    #pragma unroll
    for (int wq = 0; wq < 8; wq++) tot += red[wq];
    const float mean = tot * (1.f / (float)DMODEL);

    float vsum = 0.f;
    #pragma unroll
    for (int i = 0; i < 4; i++) {
        x[i] -= mean;
        vsum += x[i] * x[i];
    }
    #pragma unroll
    for (int off = 16; off; off >>= 1)
        vsum += __shfl_xor_sync(0xffffffffu, vsum, off);
    if ((tid & 31) == 0) red2[tid >> 5] = vsum;
    __syncthreads();
    float vtot = 0.f;
    #pragma unroll
    for (int wq = 0; wq < 8; wq++) vtot += red2[wq];
    const float rstd = rsqrtf(vtot * (1.f / (float)DMODEL) + LN_EPS);

    #pragma unroll
    for (int i = 0; i < 4; i++) {
        int c = tid + i * 256;
        out[base + c] = x[i] * rstd * g[c] + be[c];
    }
}

// ---------------------------------------------------------------------------
// Launch
// ---------------------------------------------------------------------------
extern "C" void kernel_launch(void* const* d_in, const int* in_sizes, int n_in,
                              void* d_out, int out_size)
{
    (void)in_sizes; (void)n_in; (void)out_size;

    const float* Q   = (const float*)d_in[0];
    const float* Kin = (const float*)d_in[1];
    const float* Wq  = (const float*)d_in[2];
    const float* bq  = (const float*)d_in[3];
    const float* Wk  = (const float*)d_in[4];
    const float* bk  = (const float*)d_in[5];
    const float* Wv  = (const float*)d_in[6];
    const float* bv  = (const float*)d_in[7];
    const float* Wo  = (const float*)d_in[8];
    const float* bo  = (const float*)d_in[9];
    const float* W1  = (const float*)d_in[10];
    const float* b1  = (const float*)d_in[11];
    const float* W2  = (const float*)d_in[12];
    const float* b2  = (const float*)d_in[13];
    const float* g0  = (const float*)d_in[14];
    const float* be0 = (const float*)d_in[15];
    const float* g1  = (const float*)d_in[16];
    const float* be1 = (const float*)d_in[17];
    float* out = (float*)d_out;

    float *pq, *pk, *pv, *patt, *po, *px, *pff, *py;
    cudaGetSymbolAddress((void**)&pq,   g_q);
    cudaGetSymbolAddress((void**)&pk,   g_k);
    cudaGetSymbolAddress((void**)&pv,   g_v);
    cudaGetSymbolAddress((void**)&patt, g_att);
    cudaGetSymbolAddress((void**)&po,   g_o);
    cudaGetSymbolAddress((void**)&px,   g_x);
    cudaGetSymbolAddress((void**)&pff,  g_ff);
    cudaGetSymbolAddress((void**)&py,   g_y);

    cudaFuncSetAttribute(flash_attn_tc, cudaFuncAttributeMaxDynamicSharedMemorySize,
                         FLASH_SMEM_TC);

    const dim3 blk(256);

    // QKV projections in one batched launch
    {
        GemmBatch gb;
        gb.A[0] = Q;   gb.B[0] = Wq; gb.bias[0] = bq; gb.C[0] = pq;
        gb.A[1] = Kin; gb.B[1] = Wk; gb.bias[1] = bk; gb.C[1] = pk;
        gb.A[2] = Kin; gb.B[2] = Wv; gb.bias[2] = bv; gb.C[2] = pv;
        dim3 g(DMODEL / BN, ROWS / BM, 3);
        gemm_tf32<0><<<g, blk>>>(gb, ROWS, DMODEL, DMODEL);
    }

    // multi-head attention (tensor-core)
    flash_attn_tc<<<dim3(SEQ / 64, BATCH * NHEAD), 128, FLASH_SMEM_TC>>>(pq, pk, pv, patt);

    // output projection + residual + LN0
    {
        GemmBatch gb;
        gb.A[0] = patt; gb.B[0] = Wo; gb.bias[0] = bo; gb.C[0] = po;
        dim3 g(DMODEL / BN, ROWS / BM, 1);
        gemm_tf32<0><<<g, blk>>>(gb, ROWS, DMODEL, DMODEL);
    }
    add_ln<<<ROWS, 256>>>(po, Q, g0, be0, px);

    // FFN + residual + LN1
    {
        GemmBatch gb;
        gb.A[0] = px; gb.B[0] = W1; gb.bias[0] = b1; gb.C[0] = pff;
        dim3 g(DFF_ / BN, ROWS / BM, 1);
        gemm_tf32<1><<<g, blk>>>(gb, ROWS, DFF_, DMODEL);
    }
    {
        GemmBatch gb;
        gb.A[0] = pff; gb.B[0] = W2; gb.bias[0] = b2; gb.C[0] = py;
        dim3 g(DMODEL / BN, ROWS / BM, 1);
        gemm_tf32<0><<<g, blk>>>(gb, ROWS, DMODEL, DFF_);
    }
    add_ln<<<ROWS, 256>>>(py, px, g1, be1, out);
}

// round 5
// speedup vs baseline: 3.9327x; 1.3916x over previous
#include <cuda_runtime.h>
#include <cuda_fp16.h>
#include <math.h>
#include <stdint.h>

// Problem constants
#define BATCH   4
#define SEQ     1024
#define DMODEL  1024
#define DFF_    4096
#define NHEAD   16
#define DHEAD   64
#define ROWS    (BATCH * SEQ)      // 4096
#define ATT_SCALE 0.03125f         // 1/sqrt(1024)
#define LN_EPS  1e-5f

// ---------------------------------------------------------------------------
// Scratch buffers (device globals; no dynamic allocation allowed)
// ---------------------------------------------------------------------------
__device__ float  g_q  [ROWS * DMODEL];    // Q proj (f32, for flash)
__device__ float  g_k  [ROWS * DMODEL];
__device__ float  g_v  [ROWS * DMODEL];
__device__ float  g_o  [ROWS * DMODEL];    // O proj out
__device__ float  g_x  [ROWS * DMODEL];    // LN0 out (f32, residual for LN1)
__device__ float  g_y  [ROWS * DMODEL];    // FF2 out

__device__ __half h_qi [ROWS * DMODEL];    // f16 copies of inputs Q, K
__device__ __half h_ki [ROWS * DMODEL];
__device__ __half h_att[ROWS * DMODEL];    // flash output (f16, feeds O proj)
__device__ __half h_x  [ROWS * DMODEL];    // LN0 out f16 (feeds FF1)
__device__ __half h_ff [ROWS * DFF_ ];     // FF1 out f16 (feeds FF2)
__device__ __half h_w  [12 * 1024 * 1024]; // transposed f16 weights

// ---------------------------------------------------------------------------
// PTX helpers
// ---------------------------------------------------------------------------
__device__ __forceinline__ void cp_async16(uint32_t s, const void* g) {
    asm volatile("cp.async.cg.shared.global [%0], [%1], 16;\n" :: "r"(s), "l"(g));
}
__device__ __forceinline__ uint32_t f2tf32(float f) {
    uint32_t u;
    asm("cvt.rna.tf32.f32 %0, %1;" : "=r"(u) : "f"(f));
    return u;
}
__device__ __forceinline__ float f2tf32f(float f) {
    return __uint_as_float(f2tf32(f));
}
__device__ __forceinline__ void mma_tf32(float* c, uint32_t a0, uint32_t a1,
                                         uint32_t a2, uint32_t a3,
                                         uint32_t b0, uint32_t b1) {
    asm volatile(
        "mma.sync.aligned.m16n8k8.row.col.f32.tf32.tf32.f32 "
        "{%0,%1,%2,%3}, {%4,%5,%6,%7}, {%8,%9}, {%0,%1,%2,%3};\n"
        : "+f"(c[0]), "+f"(c[1]), "+f"(c[2]), "+f"(c[3])
        : "r"(a0), "r"(a1), "r"(a2), "r"(a3), "r"(b0), "r"(b1));
}
__device__ __forceinline__ void mma_f16(float* c, uint32_t a0, uint32_t a1,
                                        uint32_t a2, uint32_t a3,
                                        uint32_t b0, uint32_t b1) {
    asm volatile(
        "mma.sync.aligned.m16n8k16.row.col.f32.f16.f16.f32 "
        "{%0,%1,%2,%3}, {%4,%5,%6,%7}, {%8,%9}, {%0,%1,%2,%3};\n"
        : "+f"(c[0]), "+f"(c[1]), "+f"(c[2]), "+f"(c[3])
        : "r"(a0), "r"(a1), "r"(a2), "r"(a3), "r"(b0), "r"(b1));
}

// ---------------------------------------------------------------------------
// Pre-pass: weight convert + transpose. src f32 [K][N] -> dst f16 [N][K].
// ---------------------------------------------------------------------------
__global__ void __launch_bounds__(256)
conv_w(const float* __restrict__ src, __half* __restrict__ dst, int K, int N)
{
    __shared__ float t[32][33];
    const int n0 = blockIdx.x * 32, k0 = blockIdx.y * 32;
    const int x = threadIdx.x & 31, y = threadIdx.x >> 5;   // 32 x 8
    #pragma unroll
    for (int j = 0; j < 4; j++)
        t[y + j * 8][x] = src[(size_t)(k0 + y + j * 8) * N + n0 + x];
    __syncthreads();
    #pragma unroll
    for (int j = 0; j < 4; j++)
        dst[(size_t)(n0 + y + j * 8) * K + k0 + x] = __float2half_rn(t[x][y + j * 8]);
}

// Pre-pass: activation convert f32 -> f16, same layout. n must be /1024.
__global__ void __launch_bounds__(256)
conv_a(const float* __restrict__ src, __half* __restrict__ dst)
{
    const size_t i = ((size_t)blockIdx.x * 256 + threadIdx.x) * 4;
    float4 v = *reinterpret_cast<const float4*>(src + i);
    __half2 lo = __floats2half2_rn(v.x, v.y);
    __half2 hi = __floats2half2_rn(v.z, v.w);
    *reinterpret_cast<__half2*>(dst + i)     = lo;
    *reinterpret_cast<__half2*>(dst + i + 2) = hi;
}

// ---------------------------------------------------------------------------
// fp16 tensor-core GEMM: C[M,N] = Ah[M,K] @ Bh[N,K]^T + bias.
// 128x128 tile, BK=32, 256 threads (8 warps, 64x32 warp tiles),
// mma.m16n8k16.f16 with f32 accum, cp.async double buffer.
// OUTH=0: f32 out (+RELU opt).  OUTH=1: f16 out only.
// Smem rows padded to 80B: fragment patterns hit all 32 banks.
// ---------------------------------------------------------------------------
struct GemmBatch {
    const __half* A[3];
    const __half* B[3];      // [N][K]
    const float*  bias[3];
    float*        C[3];
    __half*       Ch[3];
};

#define HBK 32
#define ROWB 80                       // smem row pitch bytes (32 f16 + 16B pad)
#define STAGE_BYTES (128 * ROWB)      // 10240

template<int RELU, int OUTH>
__global__ void __launch_bounds__(256)
gemm_f16(GemmBatch gb, int M, int N, int K)
{
    __shared__ __align__(128) char smem[4 * STAGE_BYTES];   // A0 A1 B0 B1

    const int z = blockIdx.z;
    const __half* __restrict__ A    = gb.A[z];
    const __half* __restrict__ Bt   = gb.B[z];
    const float*  __restrict__ bias = gb.bias[z];
    float*        __restrict__ C    = gb.C[z];
    __half*       __restrict__ Ch   = gb.Ch[z];

    const int tid  = threadIdx.x;
    const int lane = tid & 31;
    const int warp = tid >> 5;
    const int wm   = (warp >> 2) * 64;
    const int wn   = (warp & 3) * 32;
    const int crow = blockIdx.y * 128;
    const int ccol = blockIdx.x * 128;

    const __half* Ap = A  + (size_t)crow * K;
    const __half* Bp = Bt + (size_t)ccol * K;

    const uint32_t smem_base = (uint32_t)__cvta_generic_to_shared(smem);

    // per stage: each thread cp.asyncs 2 A-chunks + 2 B-chunks of 16B
    const int l_row = tid >> 2;          // 0..63 (+64)
    const int l_c16 = tid & 3;           // 16B chunk within 64B row payload

    auto load_stage = [&](int st, int k0) {
        const uint32_t as = smem_base + st * STAGE_BYTES;
        const uint32_t bs = smem_base + (2 + st) * STAGE_BYTES;
        #pragma unroll
        for (int i = 0; i < 2; i++) {
            const int row = l_row + i * 64;
            const uint32_t so = (uint32_t)(row * ROWB + l_c16 * 16);
            const size_t go = (size_t)row * K + k0 + l_c16 * 8;
            cp_async16(as + so, Ap + go);
            cp_async16(bs + so, Bp + go);
        }
        asm volatile("cp.async.commit_group;\n" ::: "memory");
    };

    float acc[4][4][4];
    #pragma unroll
    for (int mi = 0; mi < 4; mi++)
        #pragma unroll
        for (int ni = 0; ni < 4; ni++)
            #pragma unroll
            for (int r = 0; r < 4; r++) acc[mi][ni][r] = 0.f;

    const int fr = lane >> 2;
    const int fc = lane & 3;

    const int NIT = K / HBK;
    load_stage(0, 0);

    for (int it = 0; it < NIT; it++) {
        const int cur = it & 1;
        if (it + 1 < NIT) {
            load_stage(cur ^ 1, (it + 1) * HBK);
            asm volatile("cp.async.wait_group 1;\n" ::: "memory");
        } else {
            asm volatile("cp.async.wait_group 0;\n" ::: "memory");
        }
        __syncthreads();

        const char* as = smem + cur * STAGE_BYTES;
        const char* bs = smem + (2 + cur) * STAGE_BYTES;

        #pragma unroll
        for (int ks = 0; ks < 2; ks++) {
            const int kb = ks * 32;       // byte offset of k16 group
            uint32_t af[4][4];
            uint32_t bf[4][2];
            #pragma unroll
            for (int mi = 0; mi < 4; mi++) {
                const char* a = as + (wm + mi * 16 + fr) * ROWB + kb + fc * 4;
                af[mi][0] = *reinterpret_cast<const uint32_t*>(a);
                af[mi][1] = *reinterpret_cast<const uint32_t*>(a + 8 * ROWB);
                af[mi][2] = *reinterpret_cast<const uint32_t*>(a + 16);
                af[mi][3] = *reinterpret_cast<const uint32_t*>(a + 8 * ROWB + 16);
            }
            #pragma unroll
            for (int ni = 0; ni < 4; ni++) {
                const char* b = bs + (wn + ni * 8 + fr) * ROWB + kb + fc * 4;
                bf[ni][0] = *reinterpret_cast<const uint32_t*>(b);
                bf[ni][1] = *reinterpret_cast<const uint32_t*>(b + 16);
            }
            #pragma unroll
            for (int mi = 0; mi < 4; mi++)
                #pragma unroll
                for (int ni = 0; ni < 4; ni++)
                    mma_f16(acc[mi][ni], af[mi][0], af[mi][1], af[mi][2], af[mi][3],
                            bf[ni][0], bf[ni][1]);
        }
        __syncthreads();
    }

    // epilogue
    #pragma unroll
    for (int mi = 0; mi < 4; mi++) {
        #pragma unroll
        for (int ni = 0; ni < 4; ni++) {
            const int row = crow + wm + mi * 16 + fr;
            const int col = ccol + wn + ni * 8 + 2 * fc;
            const float b0 = bias[col], b1 = bias[col + 1];
            float2 v0 = make_float2(acc[mi][ni][0] + b0, acc[mi][ni][1] + b1);
            float2 v1 = make_float2(acc[mi][ni][2] + b0, acc[mi][ni][3] + b1);
            if (RELU) {
                v0.x = fmaxf(v0.x, 0.f); v0.y = fmaxf(v0.y, 0.f);
                v1.x = fmaxf(v1.x, 0.f); v1.y = fmaxf(v1.y, 0.f);
            }
            if (OUTH) {
                *reinterpret_cast<__half2*>(Ch + (size_t)row * N + col) =
                    __floats2half2_rn(v0.x, v0.y);
                *reinterpret_cast<__half2*>(Ch + (size_t)(row + 8) * N + col) =
                    __floats2half2_rn(v1.x, v1.y);
            } else {
                *reinterpret_cast<float2*>(C + (size_t)row * N + col)       = v0;
                *reinterpret_cast<float2*>(C + (size_t)(row + 8) * N + col) = v1;
            }
        }
    }
}

// ---------------------------------------------------------------------------
// Tensor-core flash attention (tf32 mma, online softmax). Output f16.
// ---------------------------------------------------------------------------
#define SK_A 68
#define SK_B 76
#define FLASH_SMEM_TC ((2 * 64 * SK_A + 2 * 64 * SK_B) * (int)sizeof(float))

__global__ void __launch_bounds__(128)
flash_attn_tc(const float* __restrict__ Q, const float* __restrict__ K,
              const float* __restrict__ V, __half* __restrict__ O)
{
    extern __shared__ float sm[];
    float* qs = sm;
    float* ps = sm + 64 * SK_A;
    float* ks = sm + 2 * 64 * SK_A;
    float* vs = ks + 64 * SK_B;

    const int tid  = threadIdx.x;
    const int lane = tid & 31;
    const int w    = tid >> 5;
    const int fr   = lane >> 2;
    const int fc   = lane & 3;

    const int qt = blockIdx.x;
    const int b  = blockIdx.y >> 4;
    const int h  = blockIdx.y & 15;

    const size_t qoff = ((size_t)b * SEQ + qt * 64) * (size_t)DMODEL + h * DHEAD;
    const size_t koff = (size_t)b * SEQ * DMODEL + h * DHEAD;

    for (int i = tid; i < 64 * 64; i += 128) {
        int r = i >> 6, c = i & 63;
        qs[r * SK_A + c] = f2tf32f(Q[qoff + (size_t)r * DMODEL + c]);
    }

    float m0 = -1e30f, m1 = -1e30f;
    float l0 = 0.f, l1 = 0.f;
    float oacc[8][4];
    #pragma unroll
    for (int ni = 0; ni < 8; ni++)
        #pragma unroll
        for (int r = 0; r < 4; r++) oacc[ni][r] = 0.f;

    const int qrow = w * 16;

    for (int kt = 0; kt < SEQ / 64; kt++) {
        __syncthreads();
        for (int i = tid; i < 64 * 64; i += 128) {
            int r = i >> 6, c = i & 63;
            size_t gofs = koff + (size_t)(kt * 64 + r) * DMODEL + c;
            ks[r * SK_B + c] = f2tf32f(K[gofs]);
            vs[r * SK_B + c] = f2tf32f(V[gofs]);
        }
        __syncthreads();

        float sacc[8][4];
        #pragma unroll
        for (int ni = 0; ni < 8; ni++)
            #pragma unroll
            for (int r = 0; r < 4; r++) sacc[ni][r] = 0.f;

        #pragma unroll
        for (int k8 = 0; k8 < 8; k8++) {
            const int kb = k8 * 8;
            const float* a = qs + (qrow + fr) * SK_A + kb + fc;
            uint32_t a0 = __float_as_uint(a[0]);
            uint32_t a1 = __float_as_uint(a[8 * SK_A]);
            uint32_t a2 = __float_as_uint(a[4]);
            uint32_t a3 = __float_as_uint(a[8 * SK_A + 4]);
            #pragma unroll
            for (int ni = 0; ni < 8; ni++) {
                const float* bp = ks + (ni * 8 + fr) * SK_B + kb + fc;
                mma_tf32(sacc[ni], a0, a1, a2, a3,
                         __float_as_uint(bp[0]), __float_as_uint(bp[4]));
            }
        }

        float mx0 = -1e30f, mx1 = -1e30f;
        #pragma unroll
        for (int ni = 0; ni < 8; ni++) {
            sacc[ni][0] *= ATT_SCALE; sacc[ni][1] *= ATT_SCALE;
            sacc[ni][2] *= ATT_SCALE; sacc[ni][3] *= ATT_SCALE;
            mx0 = fmaxf(mx0, fmaxf(sacc[ni][0], sacc[ni][1]));
            mx1 = fmaxf(mx1, fmaxf(sacc[ni][2], sacc[ni][3]));
        }
        mx0 = fmaxf(mx0, __shfl_xor_sync(0xffffffffu, mx0, 1));
        mx0 = fmaxf(mx0, __shfl_xor_sync(0xffffffffu, mx0, 2));
        mx1 = fmaxf(mx1, __shfl_xor_sync(0xffffffffu, mx1, 1));
        mx1 = fmaxf(mx1, __shfl_xor_sync(0xffffffffu, mx1, 2));

        float mn0 = fmaxf(m0, mx0), mn1 = fmaxf(m1, mx1);
        float corr0 = __expf(m0 - mn0), corr1 = __expf(m1 - mn1);
        m0 = mn0; m1 = mn1;

        float rs0 = 0.f, rs1 = 0.f;
        #pragma unroll
        for (int ni = 0; ni < 8; ni++) {
            sacc[ni][0] = __expf(sacc[ni][0] - mn0);
            sacc[ni][1] = __expf(sacc[ni][1] - mn0);
            sacc[ni][2] = __expf(sacc[ni][2] - mn1);
            sacc[ni][3] = __expf(sacc[ni][3] - mn1);
            rs0 += sacc[ni][0] + sacc[ni][1];
            rs1 += sacc[ni][2] + sacc[ni][3];
        }
        rs0 += __shfl_xor_sync(0xffffffffu, rs0, 1);
        rs0 += __shfl_xor_sync(0xffffffffu, rs0, 2);
        rs1 += __shfl_xor_sync(0xffffffffu, rs1, 1);
        rs1 += __shfl_xor_sync(0xffffffffu, rs1, 2);
        l0 = l0 * corr0 + rs0;
        l1 = l1 * corr1 + rs1;

        #pragma unroll
        for (int ni = 0; ni < 8; ni++) {
            oacc[ni][0] *= corr0; oacc[ni][1] *= corr0;
            oacc[ni][2] *= corr1; oacc[ni][3] *= corr1;
        }

        #pragma unroll
        for (int ni = 0; ni < 8; ni++) {
            float* p = ps + (qrow + fr) * SK_A + ni * 8 + 2 * fc;
            p[0]            = f2tf32f(sacc[ni][0]);
            p[1]            = f2tf32f(sacc[ni][1]);
            p[8 * SK_A]     = f2tf32f(sacc[ni][2]);
            p[8 * SK_A + 1] = f2tf32f(sacc[ni][3]);
        }
        __syncwarp();

        #pragma unroll
        for (int k8 = 0; k8 < 8; k8++) {
            const int kb = k8 * 8;
            const float* a = ps + (qrow + fr) * SK_A + kb + fc;
            uint32_t a0 = __float_as_uint(a[0]);
            uint32_t a1 = __float_as_uint(a[8 * SK_A]);
            uint32_t a2 = __float_as_uint(a[4]);
            uint32_t a3 = __float_as_uint(a[8 * SK_A + 4]);
            #pragma unroll
            for (int ni = 0; ni < 8; ni++) {
                const float* bp = vs + (kb + fc) * SK_B + ni * 8 + fr;
                mma_tf32(oacc[ni], a0, a1, a2, a3,
                         __float_as_uint(bp[0]), __float_as_uint(bp[4 * SK_B]));
            }
        }
    }

    const float inv0 = 1.f / l0;
    const float inv1 = 1.f / l1;
    const size_t row0 = (size_t)b * SEQ + qt * 64 + qrow + fr;
    const size_t row1 = row0 + 8;
    #pragma unroll
    for (int ni = 0; ni < 8; ni++) {
        const int col = h * DHEAD + ni * 8 + 2 * fc;
        *reinterpret_cast<__half2*>(O + row0 * DMODEL + col) =
            __floats2half2_rn(oacc[ni][0] * inv0, oacc[ni][1] * inv0);
        *reinterpret_cast<__half2*>(O + row1 * DMODEL + col) =
            __floats2half2_rn(oacc[ni][2] * inv1, oacc[ni][3] * inv1);
    }
}

// ---------------------------------------------------------------------------
// Fused residual add + LayerNorm (optional f16 mirror output)
// ---------------------------------------------------------------------------
template<int WH>
__global__ void __launch_bounds__(256)
add_ln(const float* __restrict__ A, const float* __restrict__ R,
       const float* __restrict__ g, const float* __restrict__ be,
       float* __restrict__ out, __half* __restrict__ outh)
{
    const int row = blockIdx.x;
    const int tid = threadIdx.x;
    const size_t base = (size_t)row * DMODEL;

    float x[4];
    float sum = 0.f;
    #pragma unroll
    for (int i = 0; i < 4; i++) {
        int c = tid + i * 256;
        x[i] = A[base + c] + R[base + c];
        sum += x[i];
    }

    __shared__ float red[8];
    __shared__ float red2[8];
    #pragma unroll
    for (int off = 16; off; off >>= 1)
        sum += __shfl_xor_sync(0xffffffffu, sum, off);
    if ((tid & 31) == 0) red[tid >> 5] = sum;
    __syncthreads();
    float tot = 0.f;
    #pragma unroll
    for (int wq = 0; wq < 8; wq++) tot += red[wq];
    const float mean = tot * (1.f / (float)DMODEL);

    float vsum = 0.f;
    #pragma unroll
    for (int i = 0; i < 4; i++) {
        x[i] -= mean;
        vsum += x[i] * x[i];
    }
    #pragma unroll
    for (int off = 16; off; off >>= 1)
        vsum += __shfl_xor_sync(0xffffffffu, vsum, off);
    if ((tid & 31) == 0) red2[tid >> 5] = vsum;
    __syncthreads();
    float vtot = 0.f;
    #pragma unroll
    for (int wq = 0; wq < 8; wq++) vtot += red2[wq];
    const float rstd = rsqrtf(vtot * (1.f / (float)DMODEL) + LN_EPS);

    #pragma unroll
    for (int i = 0; i < 4; i++) {
        int c = tid + i * 256;
        float v = x[i] * rstd * g[c] + be[c];
        out[base + c] = v;
        if (WH) outh[base + c] = __float2half_rn(v);
    }
}

// ---------------------------------------------------------------------------
// Launch
// ---------------------------------------------------------------------------
extern "C" void kernel_launch(void* const* d_in, const int* in_sizes, int n_in,
                              void* d_out, int out_size)
{
    (void)in_sizes; (void)n_in; (void)out_size;

    const float* Q   = (const float*)d_in[0];
    const float* Kin = (const float*)d_in[1];
    const float* Wq  = (const float*)d_in[2];
    const float* bq  = (const float*)d_in[3];
    const float* Wk  = (const float*)d_in[4];
    const float* bk  = (const float*)d_in[5];
    const float* Wv  = (const float*)d_in[6];
    const float* bv  = (const float*)d_in[7];
    const float* Wo  = (const float*)d_in[8];
    const float* bo  = (const float*)d_in[9];
    const float* W1  = (const float*)d_in[10];
    const float* b1  = (const float*)d_in[11];
    const float* W2  = (const float*)d_in[12];
    const float* b2  = (const float*)d_in[13];
    const float* g0  = (const float*)d_in[14];
    const float* be0 = (const float*)d_in[15];
    const float* g1  = (const float*)d_in[16];
    const float* be1 = (const float*)d_in[17];
    float* out = (float*)d_out;

    float  *pq, *pk, *pv, *po, *px, *py;
    __half *qh, *kh, *patth, *pxh, *pffh, *pw;
    cudaGetSymbolAddress((void**)&pq,    g_q);
    cudaGetSymbolAddress((void**)&pk,    g_k);
    cudaGetSymbolAddress((void**)&pv,    g_v);
    cudaGetSymbolAddress((void**)&po,    g_o);
    cudaGetSymbolAddress((void**)&px,    g_x);
    cudaGetSymbolAddress((void**)&py,    g_y);
    cudaGetSymbolAddress((void**)&qh,    h_qi);
    cudaGetSymbolAddress((void**)&kh,    h_ki);
    cudaGetSymbolAddress((void**)&patth, h_att);
    cudaGetSymbolAddress((void**)&pxh,   h_x);
    cudaGetSymbolAddress((void**)&pffh,  h_ff);
    cudaGetSymbolAddress((void**)&pw,    h_w);

    __half* wtq = pw;
    __half* wtk = pw + 1 * 1024 * 1024;
    __half* wtv = pw + 2 * 1024 * 1024;
    __half* wto = pw + 3 * 1024 * 1024;
    __half* wt1 = pw + 4 * 1024 * 1024;   // [4096][1024]
    __half* wt2 = pw + 8 * 1024 * 1024;   // [1024][4096]

    cudaFuncSetAttribute(flash_attn_tc, cudaFuncAttributeMaxDynamicSharedMemorySize,
                         FLASH_SMEM_TC);

    // pre-passes: weights (convert + transpose), activations (convert)
    conv_w<<<dim3(32, 32),  256>>>(Wq, wtq, 1024, 1024);
    conv_w<<<dim3(32, 32),  256>>>(Wk, wtk, 1024, 1024);
    conv_w<<<dim3(32, 32),  256>>>(Wv, wtv, 1024, 1024);
    conv_w<<<dim3(32, 32),  256>>>(Wo, wto, 1024, 1024);
    conv_w<<<dim3(128, 32), 256>>>(W1, wt1, 1024, 4096);
    conv_w<<<dim3(32, 128), 256>>>(W2, wt2, 4096, 1024);
    conv_a<<<ROWS * DMODEL / 1024, 256>>>(Q,   qh);
    conv_a<<<ROWS * DMODEL / 1024, 256>>>(Kin, kh);

    // QKV projections, one batched launch (f32 out for flash)
    {
        GemmBatch gb = {};
        gb.A[0] = qh; gb.B[0] = wtq; gb.bias[0] = bq; gb.C[0] = pq;
        gb.A[1] = kh; gb.B[1] = wtk; gb.bias[1] = bk; gb.C[1] = pk;
        gb.A[2] = kh; gb.B[2] = wtv; gb.bias[2] = bv; gb.C[2] = pv;
        gemm_f16<0, 0><<<dim3(8, 32, 3), 256>>>(gb, ROWS, DMODEL, DMODEL);
    }

    // multi-head attention (f16 out)
    flash_attn_tc<<<dim3(SEQ / 64, BATCH * NHEAD), 128, FLASH_SMEM_TC>>>(pq, pk, pv, patth);

    // output projection (f32 out) + residual + LN0 (f32 + f16 mirror)
    {
        GemmBatch gb = {};
        gb.A[0] = patth; gb.B[0] = wto; gb.bias[0] = bo; gb.C[0] = po;
        gemm_f16<0, 0><<<dim3(8, 32, 1), 256>>>(gb, ROWS, DMODEL, DMODEL);
    }
    add_ln<1><<<ROWS, 256>>>(po, Q, g0, be0, px, pxh);

    // FFN: FF1 (relu, f16 out), FF2 (f32 out), residual + LN1
    {
        GemmBatch gb = {};
        gb.A[0] = pxh; gb.B[0] = wt1; gb.bias[0] = b1; gb.Ch[0] = pffh;
        gemm_f16<1, 1><<<dim3(32, 32, 1), 256>>>(gb, ROWS, DFF_, DMODEL);
    }
    {
        GemmBatch gb = {};
        gb.A[0] = pffh; gb.B[0] = wt2; gb.bias[0] = b2; gb.C[0] = py;
        gemm_f16<0, 0><<<dim3(8, 32, 1), 256>>>(gb, ROWS, DMODEL, DFF_);
    }
    add_ln<0><<<ROWS, 256>>>(py, px, g1, be1, out, nullptr);
}

// round 6
// speedup vs baseline: 5.4405x; 1.3834x over previous
#include <cuda_runtime.h>
#include <cuda_fp16.h>
#include <math.h>
#include <stdint.h>

// Problem constants
#define BATCH   4
#define SEQ     1024
#define DMODEL  1024
#define DFF_    4096
#define NHEAD   16
#define DHEAD   64
#define ROWS    (BATCH * SEQ)      // 4096
#define ATT_SCALE 0.03125f         // 1/sqrt(1024)
#define LN_EPS  1e-5f

// ---------------------------------------------------------------------------
// Scratch buffers (device globals; no dynamic allocation allowed)
// ---------------------------------------------------------------------------
__device__ float  g_o  [ROWS * DMODEL];    // O proj out (f32)
__device__ float  g_x  [ROWS * DMODEL];    // LN0 out (f32 residual for LN1)
__device__ float  g_y  [ROWS * DMODEL];    // FF2 out (f32)

__device__ __half h_qi [ROWS * DMODEL];    // f16 copies of inputs Q, K
__device__ __half h_ki [ROWS * DMODEL];
__device__ __half h_q  [ROWS * DMODEL];    // QKV projections (f16)
__device__ __half h_k  [ROWS * DMODEL];
__device__ __half h_v  [ROWS * DMODEL];
__device__ __half h_vt [ROWS * DMODEL];    // V transposed per batch: [D][SEQ]
__device__ __half h_att[ROWS * DMODEL];    // flash output (f16)
__device__ __half h_x  [ROWS * DMODEL];    // LN0 out f16
__device__ __half h_ff [ROWS * DFF_ ];     // FF1 out f16
__device__ __half h_w  [12 * 1024 * 1024]; // transposed f16 weights

// ---------------------------------------------------------------------------
// PTX helpers
// ---------------------------------------------------------------------------
__device__ __forceinline__ void cp_async16(uint32_t s, const void* g) {
    asm volatile("cp.async.cg.shared.global [%0], [%1], 16;\n" :: "r"(s), "l"(g));
}
__device__ __forceinline__ void mma_f16(float* c, uint32_t a0, uint32_t a1,
                                        uint32_t a2, uint32_t a3,
                                        uint32_t b0, uint32_t b1) {
    asm volatile(
        "mma.sync.aligned.m16n8k16.row.col.f32.f16.f16.f32 "
        "{%0,%1,%2,%3}, {%4,%5,%6,%7}, {%8,%9}, {%0,%1,%2,%3};\n"
        : "+f"(c[0]), "+f"(c[1]), "+f"(c[2]), "+f"(c[3])
        : "r"(a0), "r"(a1), "r"(a2), "r"(a3), "r"(b0), "r"(b1));
}
__device__ __forceinline__ uint32_t pack_h2(float x, float y) {
    __half2 h = __floats2half2_rn(x, y);
    return *reinterpret_cast<uint32_t*>(&h);
}

// ---------------------------------------------------------------------------
// Pre-pass: weight convert + transpose. src f32 [K][N] -> dst f16 [N][K].
// ---------------------------------------------------------------------------
__global__ void __launch_bounds__(256)
conv_w(const float* __restrict__ src, __half* __restrict__ dst, int K, int N)
{
    __shared__ float t[32][33];
    const int n0 = blockIdx.x * 32, k0 = blockIdx.y * 32;
    const int x = threadIdx.x & 31, y = threadIdx.x >> 5;
    #pragma unroll
    for (int j = 0; j < 4; j++)
        t[y + j * 8][x] = src[(size_t)(k0 + y + j * 8) * N + n0 + x];
    __syncthreads();
    #pragma unroll
    for (int j = 0; j < 4; j++)
        dst[(size_t)(n0 + y + j * 8) * K + k0 + x] = __float2half_rn(t[x][y + j * 8]);
}

// Pre-pass: activation convert f32 -> f16.
__global__ void __launch_bounds__(256)
conv_a(const float* __restrict__ src, __half* __restrict__ dst)
{
    const size_t i = ((size_t)blockIdx.x * 256 + threadIdx.x) * 4;
    float4 v = *reinterpret_cast<const float4*>(src + i);
    *reinterpret_cast<__half2*>(dst + i)     = __floats2half2_rn(v.x, v.y);
    *reinterpret_cast<__half2*>(dst + i + 2) = __floats2half2_rn(v.z, v.w);
}

// Per-batch f16 transpose: dst[z][col][tok] = src[z][tok][col]   (1024x1024 each)
__global__ void __launch_bounds__(256)
vtrans(const __half* __restrict__ src, __half* __restrict__ dst)
{
    __shared__ __half t[32][33];
    const int z = blockIdx.z;
    const __half* s = src + (size_t)z * SEQ * DMODEL;
    __half*       d = dst + (size_t)z * DMODEL * SEQ;
    const int c0 = blockIdx.x * 32, r0 = blockIdx.y * 32;
    const int x = threadIdx.x & 31, y = threadIdx.x >> 5;
    #pragma unroll
    for (int j = 0; j < 4; j++)
        t[y + j * 8][x] = s[(size_t)(r0 + y + j * 8) * DMODEL + c0 + x];
    __syncthreads();
    #pragma unroll
    for (int j = 0; j < 4; j++)
        d[(size_t)(c0 + y + j * 8) * SEQ + r0 + x] = t[x][y + j * 8];
}

// ---------------------------------------------------------------------------
// fp16 tensor-core GEMM: C[M,N] = Ah[M,K] @ Bh[N,K]^T + bias.
// 128x128 tile, BK=32, 256 threads (8 warps, 64x32 warp tiles),
// mma.m16n8k16.f16, f32 accum, cp.async double buffer.
// ---------------------------------------------------------------------------
struct GemmBatch {
    const __half* A[3];
    const __half* B[3];      // [N][K]
    const float*  bias[3];
    float*        C[3];
    __half*       Ch[3];
};

#define HBK 32
#define ROWB 80
#define STAGE_BYTES (128 * ROWB)

template<int RELU, int OUTH>
__global__ void __launch_bounds__(256)
gemm_f16(GemmBatch gb, int M, int N, int K)
{
    __shared__ __align__(128) char smem[4 * STAGE_BYTES];

    const int z = blockIdx.z;
    const __half* __restrict__ A    = gb.A[z];
    const __half* __restrict__ Bt   = gb.B[z];
    const float*  __restrict__ bias = gb.bias[z];
    float*        __restrict__ C    = gb.C[z];
    __half*       __restrict__ Ch   = gb.Ch[z];

    const int tid  = threadIdx.x;
    const int lane = tid & 31;
    const int warp = tid >> 5;
    const int wm   = (warp >> 2) * 64;
    const int wn   = (warp & 3) * 32;
    const int crow = blockIdx.y * 128;
    const int ccol = blockIdx.x * 128;

    const __half* Ap = A  + (size_t)crow * K;
    const __half* Bp = Bt + (size_t)ccol * K;

    const uint32_t smem_base = (uint32_t)__cvta_generic_to_shared(smem);

    const int l_row = tid >> 2;
    const int l_c16 = tid & 3;

    auto load_stage = [&](int st, int k0) {
        const uint32_t as = smem_base + st * STAGE_BYTES;
        const uint32_t bs = smem_base + (2 + st) * STAGE_BYTES;
        #pragma unroll
        for (int i = 0; i < 2; i++) {
            const int row = l_row + i * 64;
            const uint32_t so = (uint32_t)(row * ROWB + l_c16 * 16);
            const size_t go = (size_t)row * K + k0 + l_c16 * 8;
            cp_async16(as + so, Ap + go);
            cp_async16(bs + so, Bp + go);
        }
        asm volatile("cp.async.commit_group;\n" ::: "memory");
    };

    float acc[4][4][4];
    #pragma unroll
    for (int mi = 0; mi < 4; mi++)
        #pragma unroll
        for (int ni = 0; ni < 4; ni++)
            #pragma unroll
            for (int r = 0; r < 4; r++) acc[mi][ni][r] = 0.f;

    const int fr = lane >> 2;
    const int fc = lane & 3;

    const int NIT = K / HBK;
    load_stage(0, 0);

    for (int it = 0; it < NIT; it++) {
        const int cur = it & 1;
        if (it + 1 < NIT) {
            load_stage(cur ^ 1, (it + 1) * HBK);
            asm volatile("cp.async.wait_group 1;\n" ::: "memory");
        } else {
            asm volatile("cp.async.wait_group 0;\n" ::: "memory");
        }
        __syncthreads();

        const char* as = smem + cur * STAGE_BYTES;
        const char* bs = smem + (2 + cur) * STAGE_BYTES;

        #pragma unroll
        for (int ks = 0; ks < 2; ks++) {
            const int kb = ks * 32;
            uint32_t af[4][4];
            uint32_t bf[4][2];
            #pragma unroll
            for (int mi = 0; mi < 4; mi++) {
                const char* a = as + (wm + mi * 16 + fr) * ROWB + kb + fc * 4;
                af[mi][0] = *reinterpret_cast<const uint32_t*>(a);
                af[mi][1] = *reinterpret_cast<const uint32_t*>(a + 8 * ROWB);
                af[mi][2] = *reinterpret_cast<const uint32_t*>(a + 16);
                af[mi][3] = *reinterpret_cast<const uint32_t*>(a + 8 * ROWB + 16);
            }
            #pragma unroll
            for (int ni = 0; ni < 4; ni++) {
                const char* b = bs + (wn + ni * 8 + fr) * ROWB + kb + fc * 4;
                bf[ni][0] = *reinterpret_cast<const uint32_t*>(b);
                bf[ni][1] = *reinterpret_cast<const uint32_t*>(b + 16);
            }
            #pragma unroll
            for (int mi = 0; mi < 4; mi++)
                #pragma unroll
                for (int ni = 0; ni < 4; ni++)
                    mma_f16(acc[mi][ni], af[mi][0], af[mi][1], af[mi][2], af[mi][3],
                            bf[ni][0], bf[ni][1]);
        }
        __syncthreads();
    }

    #pragma unroll
    for (int mi = 0; mi < 4; mi++) {
        #pragma unroll
        for (int ni = 0; ni < 4; ni++) {
            const int row = crow + wm + mi * 16 + fr;
            const int col = ccol + wn + ni * 8 + 2 * fc;
            const float b0 = bias[col], b1 = bias[col + 1];
            float2 v0 = make_float2(acc[mi][ni][0] + b0, acc[mi][ni][1] + b1);
            float2 v1 = make_float2(acc[mi][ni][2] + b0, acc[mi][ni][3] + b1);
            if (RELU) {
                v0.x = fmaxf(v0.x, 0.f); v0.y = fmaxf(v0.y, 0.f);
                v1.x = fmaxf(v1.x, 0.f); v1.y = fmaxf(v1.y, 0.f);
            }
            if (OUTH) {
                *reinterpret_cast<__half2*>(Ch + (size_t)row * N + col) =
                    __floats2half2_rn(v0.x, v0.y);
                *reinterpret_cast<__half2*>(Ch + (size_t)(row + 8) * N + col) =
                    __floats2half2_rn(v1.x, v1.y);
            } else {
                *reinterpret_cast<float2*>(C + (size_t)row * N + col)       = v0;
                *reinterpret_cast<float2*>(C + (size_t)(row + 8) * N + col) = v1;
            }
        }
    }
}

// ---------------------------------------------------------------------------
// f16 flash attention. 128 threads (4 warps, 16 q-rows each), q tile = 64.
// S = Q K^T and O += P V via mma.m16n8k16.f16; P stays in registers
// (S C-fragment layout == PV A-fragment layout). V pre-transposed [dh][tok].
// K/V double-buffered cp.async. Smem pitch 144B (word pitch 36 == 4 mod 32):
// all fragment load patterns conflict-free.
// ---------------------------------------------------------------------------
#define FPB 144                       // flash smem row pitch bytes (64 f16 + 16)
#define FTILE_B (64 * FPB)            // 9216 B

__global__ void __launch_bounds__(128)
flash_f16(const __half* __restrict__ Qp, const __half* __restrict__ Kp,
          const __half* __restrict__ Vt, __half* __restrict__ O)
{
    __shared__ __align__(128) char qs[FTILE_B];
    __shared__ __align__(128) char ks[2][FTILE_B];
    __shared__ __align__(128) char vs[2][FTILE_B];

    const int tid  = threadIdx.x;
    const int lane = tid & 31;
    const int w    = tid >> 5;
    const int fr   = lane >> 2;
    const int fc   = lane & 3;

    const int qt = blockIdx.x;
    const int b  = blockIdx.y >> 4;
    const int h  = blockIdx.y & 15;

    const size_t qoff = ((size_t)b * SEQ + qt * 64) * DMODEL + h * DHEAD;
    const size_t koff = (size_t)b * SEQ * DMODEL + h * DHEAD;
    const size_t voff = ((size_t)b * DMODEL + h * DHEAD) * SEQ;   // vt rows

    const uint32_t qsb = (uint32_t)__cvta_generic_to_shared(qs);
    const uint32_t ksb = (uint32_t)__cvta_generic_to_shared(ks);
    const uint32_t vsb = (uint32_t)__cvta_generic_to_shared(vs);

    // stage q once
    #pragma unroll
    for (int j = 0; j < 4; j++) {
        const int idx = tid + j * 128;
        const int row = idx >> 3, ch = idx & 7;
        cp_async16(qsb + row * FPB + ch * 16, Qp + qoff + (size_t)row * DMODEL + ch * 8);
    }
    // prefetch kt = 0
    auto stage_kv = [&](int buf, int kt) {
        #pragma unroll
        for (int j = 0; j < 4; j++) {
            const int idx = tid + j * 128;
            const int row = idx >> 3, ch = idx & 7;
            cp_async16(ksb + buf * FTILE_B + row * FPB + ch * 16,
                       Kp + koff + (size_t)(kt * 64 + row) * DMODEL + ch * 8);
            cp_async16(vsb + buf * FTILE_B + row * FPB + ch * 16,
                       Vt + voff + (size_t)row * SEQ + kt * 64 + ch * 8);
        }
        asm volatile("cp.async.commit_group;\n" ::: "memory");
    };
    stage_kv(0, 0);

    float m0 = -1e30f, m1 = -1e30f;
    float l0 = 0.f, l1 = 0.f;
    float oacc[8][4];
    #pragma unroll
    for (int ni = 0; ni < 8; ni++)
        #pragma unroll
        for (int r = 0; r < 4; r++) oacc[ni][r] = 0.f;

    const int qrow = w * 16;

    for (int kt = 0; kt < SEQ / 64; kt++) {
        const int cur = kt & 1;
        if (kt + 1 < SEQ / 64) {
            stage_kv(cur ^ 1, kt + 1);
            asm volatile("cp.async.wait_group 1;\n" ::: "memory");
        } else {
            asm volatile("cp.async.wait_group 0;\n" ::: "memory");
        }
        __syncthreads();

        const char* kb_s = ks[cur];
        const char* vb_s = vs[cur];

        // ---- S = Q K^T ----
        float sacc[8][4];
        #pragma unroll
        for (int ni = 0; ni < 8; ni++)
            #pragma unroll
            for (int r = 0; r < 4; r++) sacc[ni][r] = 0.f;

        #pragma unroll
        for (int kg = 0; kg < 4; kg++) {
            const char* a = qs + (qrow + fr) * FPB + kg * 32 + fc * 4;
            const uint32_t a0 = *reinterpret_cast<const uint32_t*>(a);
            const uint32_t a1 = *reinterpret_cast<const uint32_t*>(a + 8 * FPB);
            const uint32_t a2 = *reinterpret_cast<const uint32_t*>(a + 16);
            const uint32_t a3 = *reinterpret_cast<const uint32_t*>(a + 8 * FPB + 16);
            #pragma unroll
            for (int ni = 0; ni < 8; ni++) {
                const char* bp = kb_s + (ni * 8 + fr) * FPB + kg * 32 + fc * 4;
                mma_f16(sacc[ni], a0, a1, a2, a3,
                        *reinterpret_cast<const uint32_t*>(bp),
                        *reinterpret_cast<const uint32_t*>(bp + 16));
            }
        }

        // ---- online softmax ----
        float mx0 = -1e30f, mx1 = -1e30f;
        #pragma unroll
        for (int ni = 0; ni < 8; ni++) {
            sacc[ni][0] *= ATT_SCALE; sacc[ni][1] *= ATT_SCALE;
            sacc[ni][2] *= ATT_SCALE; sacc[ni][3] *= ATT_SCALE;
            mx0 = fmaxf(mx0, fmaxf(sacc[ni][0], sacc[ni][1]));
            mx1 = fmaxf(mx1, fmaxf(sacc[ni][2], sacc[ni][3]));
        }
        mx0 = fmaxf(mx0, __shfl_xor_sync(0xffffffffu, mx0, 1));
        mx0 = fmaxf(mx0, __shfl_xor_sync(0xffffffffu, mx0, 2));
        mx1 = fmaxf(mx1, __shfl_xor_sync(0xffffffffu, mx1, 1));
        mx1 = fmaxf(mx1, __shfl_xor_sync(0xffffffffu, mx1, 2));

        const float mn0 = fmaxf(m0, mx0), mn1 = fmaxf(m1, mx1);
        const float corr0 = __expf(m0 - mn0), corr1 = __expf(m1 - mn1);
        m0 = mn0; m1 = mn1;

        float rs0 = 0.f, rs1 = 0.f;
        #pragma unroll
        for (int ni = 0; ni < 8; ni++) {
            sacc[ni][0] = __expf(sacc[ni][0] - mn0);
            sacc[ni][1] = __expf(sacc[ni][1] - mn0);
            sacc[ni][2] = __expf(sacc[ni][2] - mn1);
            sacc[ni][3] = __expf(sacc[ni][3] - mn1);
            rs0 += sacc[ni][0] + sacc[ni][1];
            rs1 += sacc[ni][2] + sacc[ni][3];
        }
        rs0 += __shfl_xor_sync(0xffffffffu, rs0, 1);
        rs0 += __shfl_xor_sync(0xffffffffu, rs0, 2);
        rs1 += __shfl_xor_sync(0xffffffffu, rs1, 1);
        rs1 += __shfl_xor_sync(0xffffffffu, rs1, 2);
        l0 = l0 * corr0 + rs0;
        l1 = l1 * corr1 + rs1;

        #pragma unroll
        for (int ni = 0; ni < 8; ni++) {
            oacc[ni][0] *= corr0; oacc[ni][1] *= corr0;
            oacc[ni][2] *= corr1; oacc[ni][3] *= corr1;
        }

        // ---- O += P V : P from registers (C-frag == A-frag layout) ----
        #pragma unroll
        for (int kg = 0; kg < 4; kg++) {
            const uint32_t a0 = pack_h2(sacc[2 * kg][0],     sacc[2 * kg][1]);
            const uint32_t a1 = pack_h2(sacc[2 * kg][2],     sacc[2 * kg][3]);
            const uint32_t a2 = pack_h2(sacc[2 * kg + 1][0], sacc[2 * kg + 1][1]);
            const uint32_t a3 = pack_h2(sacc[2 * kg + 1][2], sacc[2 * kg + 1][3]);
            #pragma unroll
            for (int ni = 0; ni < 8; ni++) {
                const char* bp = vb_s + (ni * 8 + fr) * FPB + kg * 32 + fc * 4;
                mma_f16(oacc[ni], a0, a1, a2, a3,
                        *reinterpret_cast<const uint32_t*>(bp),
                        *reinterpret_cast<const uint32_t*>(bp + 16));
            }
        }
        __syncthreads();   // all reads of cur done before it is refilled
    }

    const float inv0 = 1.f / l0;
    const float inv1 = 1.f / l1;
    const size_t row0 = (size_t)b * SEQ + qt * 64 + qrow + fr;
    const size_t row1 = row0 + 8;
    #pragma unroll
    for (int ni = 0; ni < 8; ni++) {
        const int col = h * DHEAD + ni * 8 + 2 * fc;
        *reinterpret_cast<__half2*>(O + row0 * DMODEL + col) =
            __floats2half2_rn(oacc[ni][0] * inv0, oacc[ni][1] * inv0);
        *reinterpret_cast<__half2*>(O + row1 * DMODEL + col) =
            __floats2half2_rn(oacc[ni][2] * inv1, oacc[ni][3] * inv1);
    }
}

// ---------------------------------------------------------------------------
// Fused residual add + LayerNorm (optional f16 mirror output)
// ---------------------------------------------------------------------------
template<int WH>
__global__ void __launch_bounds__(256)
add_ln(const float* __restrict__ A, const float* __restrict__ R,
       const float* __restrict__ g, const float* __restrict__ be,
       float* __restrict__ out, __half* __restrict__ outh)
{
    const int row = blockIdx.x;
    const int tid = threadIdx.x;
    const size_t base = (size_t)row * DMODEL;

    float x[4];
    float sum = 0.f;
    #pragma unroll
    for (int i = 0; i < 4; i++) {
        int c = tid + i * 256;
        x[i] = A[base + c] + R[base + c];
        sum += x[i];
    }

    __shared__ float red[8];
    __shared__ float red2[8];
    #pragma unroll
    for (int off = 16; off; off >>= 1)
        sum += __shfl_xor_sync(0xffffffffu, sum, off);
    if ((tid & 31) == 0) red[tid >> 5] = sum;
    __syncthreads();
    float tot = 0.f;
    #pragma unroll
    for (int wq = 0; wq < 8; wq++) tot += red[wq];
    const float mean = tot * (1.f / (float)DMODEL);

    float vsum = 0.f;
    #pragma unroll
    for (int i = 0; i < 4; i++) {
        x[i] -= mean;
        vsum += x[i] * x[i];
    }
    #pragma unroll
    for (int off = 16; off; off >>= 1)
        vsum += __shfl_xor_sync(0xffffffffu, vsum, off);
    if ((tid & 31) == 0) red2[tid >> 5] = vsum;
    __syncthreads();
    float vtot = 0.f;
    #pragma unroll
    for (int wq = 0; wq < 8; wq++) vtot += red2[wq];
    const float rstd = rsqrtf(vtot * (1.f / (float)DMODEL) + LN_EPS);

    #pragma unroll
    for (int i = 0; i < 4; i++) {
        int c = tid + i * 256;
        float v = x[i] * rstd * g[c] + be[c];
        out[base + c] = v;
        if (WH) outh[base + c] = __float2half_rn(v);
    }
}

// ---------------------------------------------------------------------------
// Launch
// ---------------------------------------------------------------------------
extern "C" void kernel_launch(void* const* d_in, const int* in_sizes, int n_in,
                              void* d_out, int out_size)
{
    (void)in_sizes; (void)n_in; (void)out_size;

    const float* Q   = (const float*)d_in[0];
    const float* Kin = (const float*)d_in[1];
    const float* Wq  = (const float*)d_in[2];
    const float* bq  = (const float*)d_in[3];
    const float* Wk  = (const float*)d_in[4];
    const float* bk  = (const float*)d_in[5];
    const float* Wv  = (const float*)d_in[6];
    const float* bv  = (const float*)d_in[7];
    const float* Wo  = (const float*)d_in[8];
    const float* bo  = (const float*)d_in[9];
    const float* W1  = (const float*)d_in[10];
    const float* b1  = (const float*)d_in[11];
    const float* W2  = (const float*)d_in[12];
    const float* b2  = (const float*)d_in[13];
    const float* g0  = (const float*)d_in[14];
    const float* be0 = (const float*)d_in[15];
    const float* g1  = (const float*)d_in[16];
    const float* be1 = (const float*)d_in[17];
    float* out = (float*)d_out;

    float  *po, *px, *py;
    __half *qih, *kih, *pqh, *pkh, *pvh, *pvt, *patth, *pxh, *pffh, *pw;
    cudaGetSymbolAddress((void**)&po,    g_o);
    cudaGetSymbolAddress((void**)&px,    g_x);
    cudaGetSymbolAddress((void**)&py,    g_y);
    cudaGetSymbolAddress((void**)&qih,   h_qi);
    cudaGetSymbolAddress((void**)&kih,   h_ki);
    cudaGetSymbolAddress((void**)&pqh,   h_q);
    cudaGetSymbolAddress((void**)&pkh,   h_k);
    cudaGetSymbolAddress((void**)&pvh,   h_v);
    cudaGetSymbolAddress((void**)&pvt,   h_vt);
    cudaGetSymbolAddress((void**)&patth, h_att);
    cudaGetSymbolAddress((void**)&pxh,   h_x);
    cudaGetSymbolAddress((void**)&pffh,  h_ff);
    cudaGetSymbolAddress((void**)&pw,    h_w);

    __half* wtq = pw;
    __half* wtk = pw + 1 * 1024 * 1024;
    __half* wtv = pw + 2 * 1024 * 1024;
    __half* wto = pw + 3 * 1024 * 1024;
    __half* wt1 = pw + 4 * 1024 * 1024;
    __half* wt2 = pw + 8 * 1024 * 1024;

    // pre-passes
    conv_w<<<dim3(32, 32),  256>>>(Wq, wtq, 1024, 1024);
    conv_w<<<dim3(32, 32),  256>>>(Wk, wtk, 1024, 1024);
    conv_w<<<dim3(32, 32),  256>>>(Wv, wtv, 1024, 1024);
    conv_w<<<dim3(32, 32),  256>>>(Wo, wto, 1024, 1024);
    conv_w<<<dim3(128, 32), 256>>>(W1, wt1, 1024, 4096);
    conv_w<<<dim3(32, 128), 256>>>(W2, wt2, 4096, 1024);
    conv_a<<<ROWS * DMODEL / 1024, 256>>>(Q,   qih);
    conv_a<<<ROWS * DMODEL / 1024, 256>>>(Kin, kih);

    // QKV projections (f16 out), one batched launch
    {
        GemmBatch gb = {};
        gb.A[0] = qih; gb.B[0] = wtq; gb.bias[0] = bq; gb.Ch[0] = pqh;
        gb.A[1] = kih; gb.B[1] = wtk; gb.bias[1] = bk; gb.Ch[1] = pkh;
        gb.A[2] = kih; gb.B[2] = wtv; gb.bias[2] = bv; gb.Ch[2] = pvh;
        gemm_f16<0, 1><<<dim3(8, 32, 3), 256>>>(gb, ROWS, DMODEL, DMODEL);
    }

    // V transpose per batch, then flash attention (all f16)
    vtrans<<<dim3(32, 32, 4), 256>>>(pvh, pvt);
    flash_f16<<<dim3(SEQ / 64, BATCH * NHEAD), 128>>>(pqh, pkh, pvt, patth);

    // output projection (f32 out) + residual + LN0 (f32 + f16 mirror)
    {
        GemmBatch gb = {};
        gb.A[0] = patth; gb.B[0] = wto; gb.bias[0] = bo; gb.C[0] = po;
        gemm_f16<0, 0><<<dim3(8, 32, 1), 256>>>(gb, ROWS, DMODEL, DMODEL);
    }
    add_ln<1><<<ROWS, 256>>>(po, Q, g0, be0, px, pxh);

    // FFN
    {
        GemmBatch gb = {};
        gb.A[0] = pxh; gb.B[0] = wt1; gb.bias[0] = b1; gb.Ch[0] = pffh;
        gemm_f16<1, 1><<<dim3(32, 32, 1), 256>>>(gb, ROWS, DFF_, DMODEL);
    }
    {
        GemmBatch gb = {};
        gb.A[0] = pffh; gb.B[0] = wt2; gb.bias[0] = b2; gb.C[0] = py;
        gemm_f16<0, 0><<<dim3(8, 32, 1), 256>>>(gb, ROWS, DMODEL, DFF_);
    }
    add_ln<0><<<ROWS, 256>>>(py, px, g1, be1, out, nullptr);
}

// round 7
// speedup vs baseline: 5.9014x; 1.0847x over previous
#include <cuda_runtime.h>
#include <cuda_fp16.h>
#include <math.h>
#include <stdint.h>

// Problem constants
#define BATCH   4
#define SEQ     1024
#define DMODEL  1024
#define DFF_    4096
#define NHEAD   16
#define DHEAD   64
#define ROWS    (BATCH * SEQ)
#define LN_EPS  1e-5f
// softmax in exp2 domain: scale * log2(e)
#define SCALE_L2E (0.03125f * 1.4426950408889634f)

// ---------------------------------------------------------------------------
// Scratch buffers
// ---------------------------------------------------------------------------
__device__ float  g_o  [ROWS * DMODEL];
__device__ float  g_x  [ROWS * DMODEL];
__device__ float  g_y  [ROWS * DMODEL];

__device__ __half h_qi [ROWS * DMODEL];
__device__ __half h_ki [ROWS * DMODEL];
__device__ __half h_q  [ROWS * DMODEL];
__device__ __half h_k  [ROWS * DMODEL];
__device__ __half h_v  [ROWS * DMODEL];
__device__ __half h_vt [ROWS * DMODEL];
__device__ __half h_att[ROWS * DMODEL];
__device__ __half h_x  [ROWS * DMODEL];
__device__ __half h_ff [ROWS * DFF_ ];
__device__ __half h_w  [12 * 1024 * 1024];

// ---------------------------------------------------------------------------
// PTX helpers
// ---------------------------------------------------------------------------
__device__ __forceinline__ void cp_async16(uint32_t s, const void* g) {
    asm volatile("cp.async.cg.shared.global [%0], [%1], 16;\n" :: "r"(s), "l"(g));
}
__device__ __forceinline__ void mma_f16(float* c, uint32_t a0, uint32_t a1,
                                        uint32_t a2, uint32_t a3,
                                        uint32_t b0, uint32_t b1) {
    asm volatile(
        "mma.sync.aligned.m16n8k16.row.col.f32.f16.f16.f32 "
        "{%0,%1,%2,%3}, {%4,%5,%6,%7}, {%8,%9}, {%0,%1,%2,%3};\n"
        : "+f"(c[0]), "+f"(c[1]), "+f"(c[2]), "+f"(c[3])
        : "r"(a0), "r"(a1), "r"(a2), "r"(a3), "r"(b0), "r"(b1));
}
__device__ __forceinline__ void ldm_x4(uint32_t& r0, uint32_t& r1,
                                       uint32_t& r2, uint32_t& r3, uint32_t a) {
    asm volatile("ldmatrix.sync.aligned.m8n8.x4.shared.b16 {%0,%1,%2,%3}, [%4];"
                 : "=r"(r0), "=r"(r1), "=r"(r2), "=r"(r3) : "r"(a));
}
__device__ __forceinline__ uint32_t pack_h2(float x, float y) {
    __half2 h = __floats2half2_rn(x, y);
    return *reinterpret_cast<uint32_t*>(&h);
}

// ---------------------------------------------------------------------------
// Pre-passes
// ---------------------------------------------------------------------------
__global__ void __launch_bounds__(256)
conv_w(const float* __restrict__ src, __half* __restrict__ dst, int K, int N)
{
    __shared__ float t[32][33];
    const int n0 = blockIdx.x * 32, k0 = blockIdx.y * 32;
    const int x = threadIdx.x & 31, y = threadIdx.x >> 5;
    #pragma unroll
    for (int j = 0; j < 4; j++)
        t[y + j * 8][x] = src[(size_t)(k0 + y + j * 8) * N + n0 + x];
    __syncthreads();
    #pragma unroll
    for (int j = 0; j < 4; j++)
        dst[(size_t)(n0 + y + j * 8) * K + k0 + x] = __float2half_rn(t[x][y + j * 8]);
}

__global__ void __launch_bounds__(256)
conv_a(const float* __restrict__ src, __half* __restrict__ dst)
{
    const size_t i = ((size_t)blockIdx.x * 256 + threadIdx.x) * 4;
    float4 v = *reinterpret_cast<const float4*>(src + i);
    *reinterpret_cast<__half2*>(dst + i)     = __floats2half2_rn(v.x, v.y);
    *reinterpret_cast<__half2*>(dst + i + 2) = __floats2half2_rn(v.z, v.w);
}

__global__ void __launch_bounds__(256)
vtrans(const __half* __restrict__ src, __half* __restrict__ dst)
{
    __shared__ __half t[32][33];
    const int z = blockIdx.z;
    const __half* s = src + (size_t)z * SEQ * DMODEL;
    __half*       d = dst + (size_t)z * DMODEL * SEQ;
    const int c0 = blockIdx.x * 32, r0 = blockIdx.y * 32;
    const int x = threadIdx.x & 31, y = threadIdx.x >> 5;
    #pragma unroll
    for (int j = 0; j < 4; j++)
        t[y + j * 8][x] = s[(size_t)(r0 + y + j * 8) * DMODEL + c0 + x];
    __syncthreads();
    #pragma unroll
    for (int j = 0; j < 4; j++)
        d[(size_t)(c0 + y + j * 8) * SEQ + r0 + x] = t[x][y + j * 8];
}

// ---------------------------------------------------------------------------
// fp16 tensor-core GEMM: C[M,N] = Ah[M,K] @ Bh[N,K]^T + bias.
// 128x128 tile, BK=32, 256 threads, ldmatrix fragments, 3-stage cp.async.
// ---------------------------------------------------------------------------
struct GemmBatch {
    const __half* A[3];
    const __half* B[3];
    const float*  bias[3];
    float*        C[3];
    __half*       Ch[3];
};

#define HBK 32
#define ROWB 80
#define STAGE_BYTES (128 * ROWB)
#define GEMM_SMEM (6 * STAGE_BYTES)     // 61440

template<int RELU, int OUTH>
__global__ void __launch_bounds__(256, 2)
gemm_f16(GemmBatch gb, int M, int N, int K)
{
    extern __shared__ __align__(128) char smem[];

    const int z = blockIdx.z;
    const __half* __restrict__ A    = gb.A[z];
    const __half* __restrict__ Bt   = gb.B[z];
    const float*  __restrict__ bias = gb.bias[z];
    float*        __restrict__ C    = gb.C[z];
    __half*       __restrict__ Ch   = gb.Ch[z];

    const int tid  = threadIdx.x;
    const int lane = tid & 31;
    const int warp = tid >> 5;
    const int wm   = (warp >> 2) * 64;
    const int wn   = (warp & 3) * 32;
    const int crow = blockIdx.y * 128;
    const int ccol = blockIdx.x * 128;

    const __half* Ap = A  + (size_t)crow * K;
    const __half* Bp = Bt + (size_t)ccol * K;

    const uint32_t smem_base = (uint32_t)__cvta_generic_to_shared(smem);

    const int l_row = tid >> 2;
    const int l_c16 = tid & 3;

    // ldmatrix per-lane offsets
    const uint32_t arow_off = (uint32_t)((lane & 7) * ROWB
                            + ((lane >> 3) & 1) * 8 * ROWB + (lane >> 4) * 16);
    const uint32_t brow_off = (uint32_t)((lane & 7) * ROWB
                            + ((lane >> 3) & 1) * 16 + (lane >> 4) * 8 * ROWB);

    auto load_stage = [&](int st, int k0) {
        const uint32_t as = smem_base + st * STAGE_BYTES;
        const uint32_t bs = smem_base + (3 + st) * STAGE_BYTES;
        #pragma unroll
        for (int i = 0; i < 2; i++) {
            const int row = l_row + i * 64;
            const uint32_t so = (uint32_t)(row * ROWB + l_c16 * 16);
            const size_t go = (size_t)row * K + k0 + l_c16 * 8;
            cp_async16(as + so, Ap + go);
            cp_async16(bs + so, Bp + go);
        }
        asm volatile("cp.async.commit_group;\n" ::: "memory");
    };

    float acc[4][4][4];
    #pragma unroll
    for (int mi = 0; mi < 4; mi++)
        #pragma unroll
        for (int ni = 0; ni < 4; ni++)
            #pragma unroll
            for (int r = 0; r < 4; r++) acc[mi][ni][r] = 0.f;

    const int fr = lane >> 2;
    const int fc = lane & 3;

    const int NIT = K / HBK;
    load_stage(0, 0);
    load_stage(1, HBK);

    for (int it = 0; it < NIT; it++) {
        const int cur = it % 3;
        if (it + 1 < NIT) {
            asm volatile("cp.async.wait_group 1;\n" ::: "memory");
        } else {
            asm volatile("cp.async.wait_group 0;\n" ::: "memory");
        }
        __syncthreads();
        if (it + 2 < NIT) load_stage((it + 2) % 3, (it + 2) * HBK);

        const uint32_t as = smem_base + cur * STAGE_BYTES;
        const uint32_t bs = smem_base + (3 + cur) * STAGE_BYTES;

        #pragma unroll
        for (int ks = 0; ks < 2; ks++) {
            const int kb = ks * 32;
            uint32_t af[4][4];
            uint32_t bf[4][2];
            #pragma unroll
            for (int mi = 0; mi < 4; mi++)
                ldm_x4(af[mi][0], af[mi][1], af[mi][2], af[mi][3],
                       as + (wm + mi * 16) * ROWB + kb + arow_off);
            #pragma unroll
            for (int n2 = 0; n2 < 2; n2++)
                ldm_x4(bf[2 * n2][0], bf[2 * n2][1], bf[2 * n2 + 1][0], bf[2 * n2 + 1][1],
                       bs + (wn + n2 * 16) * ROWB + kb + brow_off);
            #pragma unroll
            for (int mi = 0; mi < 4; mi++)
                #pragma unroll
                for (int ni = 0; ni < 4; ni++)
                    mma_f16(acc[mi][ni], af[mi][0], af[mi][1], af[mi][2], af[mi][3],
                            bf[ni][0], bf[ni][1]);
        }
        __syncthreads();
    }

    #pragma unroll
    for (int mi = 0; mi < 4; mi++) {
        #pragma unroll
        for (int ni = 0; ni < 4; ni++) {
            const int row = crow + wm + mi * 16 + fr;
            const int col = ccol + wn + ni * 8 + 2 * fc;
            const float b0 = bias[col], b1 = bias[col + 1];
            float2 v0 = make_float2(acc[mi][ni][0] + b0, acc[mi][ni][1] + b1);
            float2 v1 = make_float2(acc[mi][ni][2] + b0, acc[mi][ni][3] + b1);
            if (RELU) {
                v0.x = fmaxf(v0.x, 0.f); v0.y = fmaxf(v0.y, 0.f);
                v1.x = fmaxf(v1.x, 0.f); v1.y = fmaxf(v1.y, 0.f);
            }
            if (OUTH) {
                *reinterpret_cast<__half2*>(Ch + (size_t)row * N + col) =
                    __floats2half2_rn(v0.x, v0.y);
                *reinterpret_cast<__half2*>(Ch + (size_t)(row + 8) * N + col) =
                    __floats2half2_rn(v1.x, v1.y);
            } else {
                *reinterpret_cast<float2*>(C + (size_t)row * N + col)       = v0;
                *reinterpret_cast<float2*>(C + (size_t)(row + 8) * N + col) = v1;
            }
        }
    }
}

// ---------------------------------------------------------------------------
// f16 flash attention. 256 threads (8 warps x 16 q-rows), q tile = 128.
// ldmatrix fragments; P stays in registers; V pre-transposed [dh][tok].
// Dynamic smem: q[128][144B], k[2][64][144B], v[2][64][144B] = 55296 B.
// ---------------------------------------------------------------------------
#define FPB 144
#define FKV_B (64 * FPB)                 // 9216
#define FQ_B  (128 * FPB)                // 18432
#define FLASH_SMEM (FQ_B + 4 * FKV_B)    // 55296

__global__ void __launch_bounds__(256)
flash_f16(const __half* __restrict__ Qp, const __half* __restrict__ Kp,
          const __half* __restrict__ Vt, __half* __restrict__ O)
{
    extern __shared__ __align__(128) char fsm[];
    const uint32_t qsb = (uint32_t)__cvta_generic_to_shared(fsm);
    const uint32_t ksb = qsb + FQ_B;
    const uint32_t vsb = qsb + FQ_B + 2 * FKV_B;

    const int tid  = threadIdx.x;
    const int lane = tid & 31;
    const int w    = tid >> 5;
    const int fr   = lane >> 2;
    const int fc   = lane & 3;

    const int qt = blockIdx.x;           // 0..7
    const int b  = blockIdx.y >> 4;
    const int h  = blockIdx.y & 15;

    const size_t qoff = ((size_t)b * SEQ + qt * 128) * DMODEL + h * DHEAD;
    const size_t koff = (size_t)b * SEQ * DMODEL + h * DHEAD;
    const size_t voff = ((size_t)b * DMODEL + h * DHEAD) * SEQ;

    // ldmatrix per-lane offsets (pitch FPB)
    const uint32_t arow_off = (uint32_t)((lane & 7) * FPB
                            + ((lane >> 3) & 1) * 8 * FPB + (lane >> 4) * 16);
    const uint32_t brow_off = (uint32_t)((lane & 7) * FPB
                            + ((lane >> 3) & 1) * 16 + (lane >> 4) * 8 * FPB);

    // stage q once: 128 rows x 8 chunks = 1024 / 256 thr = 4 each
    #pragma unroll
    for (int j = 0; j < 4; j++) {
        const int idx = tid + j * 256;
        const int row = idx >> 3, ch = idx & 7;
        cp_async16(qsb + row * FPB + ch * 16, Qp + qoff + (size_t)row * DMODEL + ch * 8);
    }
    auto stage_kv = [&](int buf, int kt) {
        #pragma unroll
        for (int j = 0; j < 2; j++) {
            const int idx = tid + j * 256;
            const int row = idx >> 3, ch = idx & 7;
            cp_async16(ksb + buf * FKV_B + row * FPB + ch * 16,
                       Kp + koff + (size_t)(kt * 64 + row) * DMODEL + ch * 8);
            cp_async16(vsb + buf * FKV_B + row * FPB + ch * 16,
                       Vt + voff + (size_t)row * SEQ + kt * 64 + ch * 8);
        }
        asm volatile("cp.async.commit_group;\n" ::: "memory");
    };
    stage_kv(0, 0);

    float m0 = -1e30f, m1 = -1e30f;
    float l0 = 0.f, l1 = 0.f;
    float oacc[8][4];
    #pragma unroll
    for (int ni = 0; ni < 8; ni++)
        #pragma unroll
        for (int r = 0; r < 4; r++) oacc[ni][r] = 0.f;

    const int qrow = w * 16;

    for (int kt = 0; kt < SEQ / 64; kt++) {
        const int cur = kt & 1;
        if (kt + 1 < SEQ / 64) {
            stage_kv(cur ^ 1, kt + 1);
            asm volatile("cp.async.wait_group 1;\n" ::: "memory");
        } else {
            asm volatile("cp.async.wait_group 0;\n" ::: "memory");
        }
        __syncthreads();

        const uint32_t kb_s = ksb + cur * FKV_B;
        const uint32_t vb_s = vsb + cur * FKV_B;

        // ---- S = Q K^T ----
        float sacc[8][4];
        #pragma unroll
        for (int ni = 0; ni < 8; ni++)
            #pragma unroll
            for (int r = 0; r < 4; r++) sacc[ni][r] = 0.f;

        #pragma unroll
        for (int kg = 0; kg < 4; kg++) {
            const int kb = kg * 32;
            uint32_t a0, a1, a2, a3;
            ldm_x4(a0, a1, a2, a3, qsb + qrow * FPB + kb + arow_off);
            uint32_t bf[8][2];
            #pragma unroll
            for (int n2 = 0; n2 < 4; n2++)
                ldm_x4(bf[2 * n2][0], bf[2 * n2][1], bf[2 * n2 + 1][0], bf[2 * n2 + 1][1],
                       kb_s + (n2 * 16) * FPB + kb + brow_off);
            #pragma unroll
            for (int ni = 0; ni < 8; ni++)
                mma_f16(sacc[ni], a0, a1, a2, a3, bf[ni][0], bf[ni][1]);
        }

        // ---- online softmax (exp2 domain) ----
        float mx0 = -1e30f, mx1 = -1e30f;
        #pragma unroll
        for (int ni = 0; ni < 8; ni++) {
            sacc[ni][0] *= SCALE_L2E; sacc[ni][1] *= SCALE_L2E;
            sacc[ni][2] *= SCALE_L2E; sacc[ni][3] *= SCALE_L2E;
            mx0 = fmaxf(mx0, fmaxf(sacc[ni][0], sacc[ni][1]));
            mx1 = fmaxf(mx1, fmaxf(sacc[ni][2], sacc[ni][3]));
        }
        mx0 = fmaxf(mx0, __shfl_xor_sync(0xffffffffu, mx0, 1));
        mx0 = fmaxf(mx0, __shfl_xor_sync(0xffffffffu, mx0, 2));
        mx1 = fmaxf(mx1, __shfl_xor_sync(0xffffffffu, mx1, 1));
        mx1 = fmaxf(mx1, __shfl_xor_sync(0xffffffffu, mx1, 2));

        const float mn0 = fmaxf(m0, mx0), mn1 = fmaxf(m1, mx1);
        const float corr0 = exp2f(m0 - mn0), corr1 = exp2f(m1 - mn1);
        m0 = mn0; m1 = mn1;

        float rs0 = 0.f, rs1 = 0.f;
        #pragma unroll
        for (int ni = 0; ni < 8; ni++) {
            sacc[ni][0] = exp2f(sacc[ni][0] - mn0);
            sacc[ni][1] = exp2f(sacc[ni][1] - mn0);
            sacc[ni][2] = exp2f(sacc[ni][2] - mn1);
            sacc[ni][3] = exp2f(sacc[ni][3] - mn1);
            rs0 += sacc[ni][0] + sacc[ni][1];
            rs1 += sacc[ni][2] + sacc[ni][3];
        }
        rs0 += __shfl_xor_sync(0xffffffffu, rs0, 1);
        rs0 += __shfl_xor_sync(0xffffffffu, rs0, 2);
        rs1 += __shfl_xor_sync(0xffffffffu, rs1, 1);
        rs1 += __shfl_xor_sync(0xffffffffu, rs1, 2);
        l0 = l0 * corr0 + rs0;
        l1 = l1 * corr1 + rs1;

        #pragma unroll
        for (int ni = 0; ni < 8; ni++) {
            oacc[ni][0] *= corr0; oacc[ni][1] *= corr0;
            oacc[ni][2] *= corr1; oacc[ni][3] *= corr1;
        }

        // ---- O += P V ----
        #pragma unroll
        for (int kg = 0; kg < 4; kg++) {
            const int kb = kg * 32;
            const uint32_t a0 = pack_h2(sacc[2 * kg][0],     sacc[2 * kg][1]);
            const uint32_t a1 = pack_h2(sacc[2 * kg][2],     sacc[2 * kg][3]);
            const uint32_t a2 = pack_h2(sacc[2 * kg + 1][0], sacc[2 * kg + 1][1]);
            const uint32_t a3 = pack_h2(sacc[2 * kg + 1][2], sacc[2 * kg + 1][3]);
            uint32_t bf[8][2];
            #pragma unroll
            for (int n2 = 0; n2 < 4; n2++)
                ldm_x4(bf[2 * n2][0], bf[2 * n2][1], bf[2 * n2 + 1][0], bf[2 * n2 + 1][1],
                       vb_s + (n2 * 16) * FPB + kb + brow_off);
            #pragma unroll
            for (int ni = 0; ni < 8; ni++)
                mma_f16(oacc[ni], a0, a1, a2, a3, bf[ni][0], bf[ni][1]);
        }
        __syncthreads();
    }

    const float inv0 = 1.f / l0;
    const float inv1 = 1.f / l1;
    const size_t row0 = (size_t)b * SEQ + qt * 128 + qrow + fr;
    const size_t row1 = row0 + 8;
    #pragma unroll
    for (int ni = 0; ni < 8; ni++) {
        const int col = h * DHEAD + ni * 8 + 2 * fc;
        *reinterpret_cast<__half2*>(O + row0 * DMODEL + col) =
            __floats2half2_rn(oacc[ni][0] * inv0, oacc[ni][1] * inv0);
        *reinterpret_cast<__half2*>(O + row1 * DMODEL + col) =
            __floats2half2_rn(oacc[ni][2] * inv1, oacc[ni][3] * inv1);
    }
}

// ---------------------------------------------------------------------------
// Fused residual add + LayerNorm
// ---------------------------------------------------------------------------
template<int WH>
__global__ void __launch_bounds__(256)
add_ln(const float* __restrict__ A, const float* __restrict__ R,
       const float* __restrict__ g, const float* __restrict__ be,
       float* __restrict__ out, __half* __restrict__ outh)
{
    const int row = blockIdx.x;
    const int tid = threadIdx.x;
    const size_t base = (size_t)row * DMODEL;

    float x[4];
    float sum = 0.f;
    #pragma unroll
    for (int i = 0; i < 4; i++) {
        int c = tid + i * 256;
        x[i] = A[base + c] + R[base + c];
        sum += x[i];
    }

    __shared__ float red[8];
    __shared__ float red2[8];
    #pragma unroll
    for (int off = 16; off; off >>= 1)
        sum += __shfl_xor_sync(0xffffffffu, sum, off);
    if ((tid & 31) == 0) red[tid >> 5] = sum;
    __syncthreads();
    float tot = 0.f;
    #pragma unroll
    for (int wq = 0; wq < 8; wq++) tot += red[wq];
    const float mean = tot * (1.f / (float)DMODEL);

    float vsum = 0.f;
    #pragma unroll
    for (int i = 0; i < 4; i++) {
        x[i] -= mean;
        vsum += x[i] * x[i];
    }
    #pragma unroll
    for (int off = 16; off; off >>= 1)
        vsum += __shfl_xor_sync(0xffffffffu, vsum, off);
    if ((tid & 31) == 0) red2[tid >> 5] = vsum;
    __syncthreads();
    float vtot = 0.f;
    #pragma unroll
    for (int wq = 0; wq < 8; wq++) vtot += red2[wq];
    const float rstd = rsqrtf(vtot * (1.f / (float)DMODEL) + LN_EPS);

    #pragma unroll
    for (int i = 0; i < 4; i++) {
        int c = tid + i * 256;
        float v = x[i] * rstd * g[c] + be[c];
        out[base + c] = v;
        if (WH) outh[base + c] = __float2half_rn(v);
    }
}

// ---------------------------------------------------------------------------
// Launch
// ---------------------------------------------------------------------------
extern "C" void kernel_launch(void* const* d_in, const int* in_sizes, int n_in,
                              void* d_out, int out_size)
{
    (void)in_sizes; (void)n_in; (void)out_size;

    const float* Q   = (const float*)d_in[0];
    const float* Kin = (const float*)d_in[1];
    const float* Wq  = (const float*)d_in[2];
    const float* bq  = (const float*)d_in[3];
    const float* Wk  = (const float*)d_in[4];
    const float* bk  = (const float*)d_in[5];
    const float* Wv  = (const float*)d_in[6];
    const float* bv  = (const float*)d_in[7];
    const float* Wo  = (const float*)d_in[8];
    const float* bo  = (const float*)d_in[9];
    const float* W1  = (const float*)d_in[10];
    const float* b1  = (const float*)d_in[11];
    const float* W2  = (const float*)d_in[12];
    const float* b2  = (const float*)d_in[13];
    const float* g0  = (const float*)d_in[14];
    const float* be0 = (const float*)d_in[15];
    const float* g1  = (const float*)d_in[16];
    const float* be1 = (const float*)d_in[17];
    float* out = (float*)d_out;

    float  *po, *px, *py;
    __half *qih, *kih, *pqh, *pkh, *pvh, *pvt, *patth, *pxh, *pffh, *pw;
    cudaGetSymbolAddress((void**)&po,    g_o);
    cudaGetSymbolAddress((void**)&px,    g_x);
    cudaGetSymbolAddress((void**)&py,    g_y);
    cudaGetSymbolAddress((void**)&qih,   h_qi);
    cudaGetSymbolAddress((void**)&kih,   h_ki);
    cudaGetSymbolAddress((void**)&pqh,   h_q);
    cudaGetSymbolAddress((void**)&pkh,   h_k);
    cudaGetSymbolAddress((void**)&pvh,   h_v);
    cudaGetSymbolAddress((void**)&pvt,   h_vt);
    cudaGetSymbolAddress((void**)&patth, h_att);
    cudaGetSymbolAddress((void**)&pxh,   h_x);
    cudaGetSymbolAddress((void**)&pffh,  h_ff);
    cudaGetSymbolAddress((void**)&pw,    h_w);

    __half* wtq = pw;
    __half* wtk = pw + 1 * 1024 * 1024;
    __half* wtv = pw + 2 * 1024 * 1024;
    __half* wto = pw + 3 * 1024 * 1024;
    __half* wt1 = pw + 4 * 1024 * 1024;
    __half* wt2 = pw + 8 * 1024 * 1024;

    cudaFuncSetAttribute(gemm_f16<0, 0>, cudaFuncAttributeMaxDynamicSharedMemorySize, GEMM_SMEM);
    cudaFuncSetAttribute(gemm_f16<0, 1>, cudaFuncAttributeMaxDynamicSharedMemorySize, GEMM_SMEM);
    cudaFuncSetAttribute(gemm_f16<1, 1>, cudaFuncAttributeMaxDynamicSharedMemorySize, GEMM_SMEM);
    cudaFuncSetAttribute(flash_f16, cudaFuncAttributeMaxDynamicSharedMemorySize, FLASH_SMEM);

    // pre-passes
    conv_w<<<dim3(32, 32),  256>>>(Wq, wtq, 1024, 1024);
    conv_w<<<dim3(32, 32),  256>>>(Wk, wtk, 1024, 1024);
    conv_w<<<dim3(32, 32),  256>>>(Wv, wtv, 1024, 1024);
    conv_w<<<dim3(32, 32),  256>>>(Wo, wto, 1024, 1024);
    conv_w<<<dim3(128, 32), 256>>>(W1, wt1, 1024, 4096);
    conv_w<<<dim3(32, 128), 256>>>(W2, wt2, 4096, 1024);
    conv_a<<<ROWS * DMODEL / 1024, 256>>>(Q,   qih);
    conv_a<<<ROWS * DMODEL / 1024, 256>>>(Kin, kih);

    // QKV projections (f16 out)
    {
        GemmBatch gb = {};
        gb.A[0] = qih; gb.B[0] = wtq; gb.bias[0] = bq; gb.Ch[0] = pqh;
        gb.A[1] = kih; gb.B[1] = wtk; gb.bias[1] = bk; gb.Ch[1] = pkh;
        gb.A[2] = kih; gb.B[2] = wtv; gb.bias[2] = bv; gb.Ch[2] = pvh;
        gemm_f16<0, 1><<<dim3(8, 32, 3), 256, GEMM_SMEM>>>(gb, ROWS, DMODEL, DMODEL);
    }

    // V transpose, flash attention
    vtrans<<<dim3(32, 32, 4), 256>>>(pvh, pvt);
    flash_f16<<<dim3(SEQ / 128, BATCH * NHEAD), 256, FLASH_SMEM>>>(pqh, pkh, pvt, patth);

    // output projection + residual + LN0
    {
        GemmBatch gb = {};
        gb.A[0] = patth; gb.B[0] = wto; gb.bias[0] = bo; gb.C[0] = po;
        gemm_f16<0, 0><<<dim3(8, 32, 1), 256, GEMM_SMEM>>>(gb, ROWS, DMODEL, DMODEL);
    }
    add_ln<1><<<ROWS, 256>>>(po, Q, g0, be0, px, pxh);

    // FFN
    {
        GemmBatch gb = {};
        gb.A[0] = pxh; gb.B[0] = wt1; gb.bias[0] = b1; gb.Ch[0] = pffh;
        gemm_f16<1, 1><<<dim3(32, 32, 1), 256, GEMM_SMEM>>>(gb, ROWS, DFF_, DMODEL);
    }
    {
        GemmBatch gb = {};
        gb.A[0] = pffh; gb.B[0] = wt2; gb.bias[0] = b2; gb.C[0] = py;
        gemm_f16<0, 0><<<dim3(8, 32, 1), 256, GEMM_SMEM>>>(gb, ROWS, DMODEL, DFF_);
    }
    add_ln<0><<<ROWS, 256>>>(py, px, g1, be1, out, nullptr);
}